// round 10
// baseline (speedup 1.0000x reference)
#include <cuda_runtime.h>
#include <math.h>
#include <stdint.h>

#define BEPS 1e-5f
#define NB 4096

// ---------------- scratch (allocation-free) ----------------
__device__ float h2_g[NB * 784];
__device__ float h3T_g[(size_t)NB * 25 * 256];        // [(b*25+pos)][d]
__device__ uint32_t h3T_hi_g[(size_t)NB * 25 * 256];  // tf32 hi
__device__ uint32_t h3T_lo_g[(size_t)NB * 25 * 256];  // tf32 lo
__device__ float xp_g[(size_t)NB * 25 * 512];         // [(b*25+pos)][p]
__device__ float w_g[NB * 512];
__device__ uint32_t z_hi_g[NB * 256];
__device__ uint32_t z_lo_g[NB * 256];
__device__ float up2_g[(size_t)NB * 6400];            // [(b*25+pos)][c]
__device__ float G_g[(size_t)NB * 25 * 144];          // [(b*25+pos)][o*9+tap]
__device__ float protoT_g[256 * 512];                 // [d][p] raw (z_gemm B)
__device__ uint32_t protoT_hi_g[256 * 512];           // [k][n] tf32 hi
__device__ uint32_t protoT_lo_g[256 * 512];
__device__ uint32_t wupPT_hi_g[256 * 6400];           // [k][pos*256+c]
__device__ uint32_t wupPT_lo_g[256 * 6400];
__device__ float pp_g[512];                           // sum_d proto^2
__device__ float w3t_g[256 * 144];                    // [(c*9+tap)][oc]

// ---------------- packed fp32x2 helpers ----------------
static __device__ __forceinline__ unsigned long long ffma2(
    unsigned long long a, unsigned long long b, unsigned long long c) {
    unsigned long long d;
    asm("fma.rn.f32x2 %0, %1, %2, %3;" : "=l"(d) : "l"(a), "l"(b), "l"(c));
    return d;
}
static __device__ __forceinline__ unsigned long long pack2(float x, float y) {
    unsigned long long r;
    asm("mov.b64 %0, {%1, %2};" : "=l"(r) : "f"(x), "f"(y));
    return r;
}
static __device__ __forceinline__ float2 unpack2(unsigned long long v) {
    float2 r;
    asm("mov.b64 {%0, %1}, %2;" : "=f"(r.x), "=f"(r.y) : "l"(v));
    return r;
}

// ---------------- tf32 helpers ----------------
static __device__ __forceinline__ void cvt_hilo(float x, uint32_t& hi, uint32_t& lo) {
    uint32_t h;
    asm("cvt.rna.tf32.f32 %0, %1;" : "=r"(h) : "f"(x));
    float hf = __uint_as_float(h);
    float l = x - hf;
    asm("cvt.rna.tf32.f32 %0, %1;" : "=r"(lo) : "f"(l));
    hi = h;
}
static __device__ __forceinline__ void mma_tf32(float* c, const uint32_t* a, const uint32_t* b) {
    asm volatile(
        "mma.sync.aligned.m16n8k8.row.col.f32.tf32.tf32.f32 "
        "{%0,%1,%2,%3}, {%4,%5,%6,%7}, {%8,%9}, {%0,%1,%2,%3};"
        : "+f"(c[0]), "+f"(c[1]), "+f"(c[2]), "+f"(c[3])
        : "r"(a[0]), "r"(a[1]), "r"(a[2]), "r"(a[3]), "r"(b[0]), "r"(b[1]));
}

// ---------------- cp.async helpers ----------------
static __device__ __forceinline__ uint32_t smem_u32(const void* p) {
    uint32_t a;
    asm("{ .reg .u64 t; cvta.to.shared.u64 t, %1; cvt.u32.u64 %0, t; }" : "=r"(a) : "l"(p));
    return a;
}
#define CPASYNC16(dst, src) \
    asm volatile("cp.async.cg.shared.global [%0], [%1], 16;" :: "r"(dst), "l"(src) : "memory")
#define CPCOMMIT() asm volatile("cp.async.commit_group;" ::: "memory")
#define CPWAIT1() asm volatile("cp.async.wait_group 1;" ::: "memory")
#define CPWAIT0() asm volatile("cp.async.wait_group 0;" ::: "memory")

// ---------------------------------------------------------------------------
// prep: hi/lo splits + transposes + proto norms
// ---------------------------------------------------------------------------
__global__ void prep_kernel(const float* __restrict__ proto,
                            const float* __restrict__ w3,
                            const float* __restrict__ wup)
{
    int stride = gridDim.x * blockDim.x;
    int tid = blockIdx.x * blockDim.x + threadIdx.x;
    // protoT raw + hi/lo: [d][p]
    for (int i = tid; i < 512 * 256; i += stride) {
        int d = i >> 9, p = i & 511;
        float v = proto[p * 256 + d];
        protoT_g[i] = v;
        uint32_t hi, lo;
        cvt_hilo(v, hi, lo);
        protoT_hi_g[i] = hi;
        protoT_lo_g[i] = lo;
    }
    for (int p = tid; p < 512; p += stride) {
        float s = 0.f;
        for (int d = 0; d < 256; d++) {
            float v = proto[p * 256 + d];
            s += v * v;
        }
        pp_g[p] = s;
    }
    for (int i = tid; i < 256 * 144; i += stride) {
        int o = i & 255, ct = i >> 8;
        int c = ct / 9, tap = ct - c * 9;
        w3t_g[i] = w3[o * 144 + c * 9 + tap];
    }
    // wupPT[k][pos*256+c] = wup[k][c*25+pos], hi/lo
    for (int i = tid; i < 256 * 6400; i += stride) {
        int k = i / 6400, rr = i % 6400;
        int pos = rr >> 8, c = rr & 255;
        float v = wup[(size_t)k * 6400 + c * 25 + pos];
        uint32_t hi, lo;
        cvt_hilo(v, hi, lo);
        wupPT_hi_g[i] = hi;
        wupPT_lo_g[i] = lo;
    }
}

// ---------------------------------------------------------------------------
// enc12: conv1 + conv2, one block per image
// ---------------------------------------------------------------------------
__global__ __launch_bounds__(128) void enc12_kernel(
    const float* __restrict__ x,
    const float* __restrict__ w1, const float* __restrict__ b1,
    const float* __restrict__ w2, const float* __restrict__ b2,
    const float* __restrict__ g2, const float* __restrict__ bt2)
{
    __shared__ float xs[784];
    __shared__ float h1s[8 * 196];
    const int b = blockIdx.x;
    const int t = threadIdx.x;

    const float* xb = x + b * 784;
    for (int i = t; i < 784; i += 128) xs[i] = xb[i];
    __syncthreads();

    for (int idx = t; idx < 1568; idx += 128) {
        int o = idx / 196, r = idx % 196, i = r / 14, j = r % 14;
        float acc = b1[o];
        #pragma unroll
        for (int ky = 0; ky < 3; ky++) {
            int y = 2 * i - 1 + ky;
            if ((unsigned)y >= 28u) continue;
            #pragma unroll
            for (int kx = 0; kx < 3; kx++) {
                int xx = 2 * j - 1 + kx;
                if ((unsigned)xx >= 28u) continue;
                acc += xs[y * 28 + xx] * w1[o * 9 + ky * 3 + kx];
            }
        }
        h1s[idx] = fmaxf(acc, 0.f);
    }
    __syncthreads();

    const float rs = rsqrtf(1.f + BEPS);
    for (int idx = t; idx < 784; idx += 128) {
        int o = idx / 49, r = idx % 49, i = r / 7, j = r % 7;
        float acc = 0.f;
        for (int c = 0; c < 8; c++) {
            #pragma unroll
            for (int ky = 0; ky < 3; ky++) {
                int y = 2 * i - 1 + ky;
                if ((unsigned)y >= 14u) continue;
                #pragma unroll
                for (int kx = 0; kx < 3; kx++) {
                    int xx = 2 * j - 1 + kx;
                    if ((unsigned)xx >= 14u) continue;
                    acc += h1s[c * 196 + y * 14 + xx] * w2[((o * 8 + c) * 3 + ky) * 3 + kx];
                }
            }
        }
        float s = g2[o] * rs;
        h2_g[b * 784 + idx] = fmaxf((acc + b2[o]) * s + bt2[o], 0.f);
    }
}

// ---------------------------------------------------------------------------
// conv3: 16->256 k3 s1 p0, 7->5; writes h3T raw + tf32 hi/lo
// ---------------------------------------------------------------------------
__global__ __launch_bounds__(256, 2) void conv3_kernel(const float* __restrict__ b3)
{
    __shared__ float h2s[784];
    const int b = blockIdx.x;
    const int t = threadIdx.x;

    for (int i = t; i < 784; i += 256) h2s[i] = h2_g[b * 784 + i];
    __syncthreads();

    float acc[25];
    #pragma unroll
    for (int p = 0; p < 25; p++) acc[p] = 0.f;

    for (int c = 0; c < 16; c++) {
        float w[9];
        #pragma unroll
        for (int tap = 0; tap < 9; tap++) w[tap] = w3t_g[(c * 9 + tap) * 256 + t];
        float h[49];
        #pragma unroll
        for (int i = 0; i < 49; i++) h[i] = h2s[c * 49 + i];
        #pragma unroll
        for (int ky = 0; ky < 3; ky++)
            #pragma unroll
            for (int kx = 0; kx < 3; kx++) {
                float wv = w[ky * 3 + kx];
                #pragma unroll
                for (int i = 0; i < 5; i++)
                    #pragma unroll
                    for (int j = 0; j < 5; j++)
                        acc[i * 5 + j] += wv * h[(i + ky) * 7 + (j + kx)];
            }
    }
    float bb = b3[t];
    #pragma unroll
    for (int p = 0; p < 25; p++) {
        float v = fmaxf(acc[p] + bb, 0.f);
        size_t idx = ((size_t)b * 25 + p) * 256 + t;
        h3T_g[idx] = v;
        uint32_t hi, lo;
        cvt_hilo(v, hi, lo);
        h3T_hi_g[idx] = hi;
        h3T_lo_g[idx] = lo;
    }
}

// ===========================================================================
// 3xTF32 GEMM cores with PRE-SPLIT hi/lo operands — no cvt in the mainloop.
// Block 128x128, 8 warps (4m x 2n), warp tile 32x64, k-chunk 16, 2 stages.
// ===========================================================================
#define ASTR 20                      // 16 + 4 pad (conflict-free: 20r+c distinct)
#define BSTR 136                     // 128 + 8 pad (8r+c distinct)
#define ASTG16 (128 * ASTR)          // 2560
#define BSTG16 (16 * BSTR)           // 2176
// smem: Ah[2] Al[2] Bh[2] Bl[2]
#define OFF_AL (2 * ASTG16)
#define OFF_BH (4 * ASTG16)
#define OFF_BL (4 * ASTG16 + 2 * BSTG16)
#define PIPE_SMEM ((4 * ASTG16 + 4 * BSTG16) * 4)   // 75,776 bytes

// generic mainloop macro body shared by xp and up via inline function
static __device__ __forceinline__ void gemm_hilo_core(
    uint32_t* smp,
    const uint32_t* __restrict__ gAh, const uint32_t* __restrict__ gAl, size_t arow0,
    const uint32_t* __restrict__ gBh, const uint32_t* __restrict__ gBl, size_t bcol0,
    int ldb, float acc[2][8][4], int t)
{
    const int lane = t & 31, wid = t >> 5;
    const int wm = wid & 3, wn = wid >> 2;

    const int ar = t >> 1, ak = (t & 1) * 8;     // A loader: 2 thr/row, 8 cols each
    const int br = t >> 4, bn8 = (t & 15) * 8;   // B loader: 16 thr/row, 8 cols each
    const uint32_t smb = smem_u32(smp);
    const uint32_t sAh = smb + (uint32_t)(ar * ASTR + ak) * 4;
    const uint32_t sAl = sAh + OFF_AL * 4;
    const uint32_t sBh = smb + (uint32_t)(OFF_BH + br * BSTR + bn8) * 4;
    const uint32_t sBl = sBh + 2 * BSTG16 * 4;
    const uint32_t* pAh = gAh + arow0 * 256 + ak + (size_t)(ar - ar) ; // placeholder
    (void)pAh;
    const uint32_t* gA_h = gAh + (arow0 + ar) * 256 + ak;
    const uint32_t* gA_l = gAl + (arow0 + ar) * 256 + ak;
    const uint32_t* gB_h = gBh + (size_t)br * ldb + bcol0 + bn8;
    const uint32_t* gB_l = gBl + (size_t)br * ldb + bcol0 + bn8;

    // prefetch chunk 0 -> stage 0
    CPASYNC16(sAh, gA_h);          CPASYNC16(sAh + 16, gA_h + 4);
    CPASYNC16(sAl, gA_l);          CPASYNC16(sAl + 16, gA_l + 4);
    CPASYNC16(sBh, gB_h);          CPASYNC16(sBh + 16, gB_h + 4);
    CPASYNC16(sBl, gB_l);          CPASYNC16(sBl + 16, gB_l + 4);
    CPCOMMIT();

    for (int c = 0; c < 16; c++) {
        if (c < 15) {
            const int k0 = (c + 1) * 16;
            const uint32_t st = (uint32_t)((c + 1) & 1);
            uint32_t dAh = sAh + st * ASTG16 * 4;
            uint32_t dAl = sAl + st * ASTG16 * 4;
            uint32_t dBh = sBh + st * BSTG16 * 4;
            uint32_t dBl = sBl + st * BSTG16 * 4;
            CPASYNC16(dAh, gA_h + k0);      CPASYNC16(dAh + 16, gA_h + k0 + 4);
            CPASYNC16(dAl, gA_l + k0);      CPASYNC16(dAl + 16, gA_l + k0 + 4);
            CPASYNC16(dBh, gB_h + (size_t)k0 * ldb);
            CPASYNC16(dBh + 16, gB_h + (size_t)k0 * ldb + 4);
            CPASYNC16(dBl, gB_l + (size_t)k0 * ldb);
            CPASYNC16(dBl + 16, gB_l + (size_t)k0 * ldb + 4);
            CPCOMMIT();
            CPWAIT1();
        } else {
            CPWAIT0();
        }
        __syncthreads();

        const uint32_t st = (uint32_t)(c & 1);
        const uint32_t* Ah = smp + st * ASTG16;
        const uint32_t* Al = Ah + OFF_AL;
        const uint32_t* Bh = smp + OFF_BH + st * BSTG16;
        const uint32_t* Bl = Bh + 2 * BSTG16;

        #pragma unroll
        for (int ks = 0; ks < 2; ks++) {
            const int col = ks * 8 + (lane & 3);
            uint32_t ah[2][4], al[2][4];
            #pragma unroll
            for (int ms = 0; ms < 2; ms++) {
                int mb = wm * 32 + ms * 16 + (lane >> 2);
                ah[ms][0] = Ah[mb * ASTR + col];
                ah[ms][1] = Ah[(mb + 8) * ASTR + col];
                ah[ms][2] = Ah[mb * ASTR + col + 4];
                ah[ms][3] = Ah[(mb + 8) * ASTR + col + 4];
                al[ms][0] = Al[mb * ASTR + col];
                al[ms][1] = Al[(mb + 8) * ASTR + col];
                al[ms][2] = Al[mb * ASTR + col + 4];
                al[ms][3] = Al[(mb + 8) * ASTR + col + 4];
            }
            const int row = ks * 8 + (lane & 3);
            #pragma unroll
            for (int nt = 0; nt < 8; nt++) {
                int nb = wn * 64 + nt * 8 + (lane >> 2);
                uint32_t bh[2], bl[2];
                bh[0] = Bh[row * BSTR + nb];
                bh[1] = Bh[(row + 4) * BSTR + nb];
                bl[0] = Bl[row * BSTR + nb];
                bl[1] = Bl[(row + 4) * BSTR + nb];
                #pragma unroll
                for (int ms = 0; ms < 2; ms++) {
                    mma_tf32(acc[ms][nt], ah[ms], bh);
                    mma_tf32(acc[ms][nt], ah[ms], bl);
                    mma_tf32(acc[ms][nt], al[ms], bh);
                }
            }
        }
        __syncthreads();
    }
}

// xp GEMM: C[102400x512] = h3T * protoT  (A,B pre-split hi/lo)
__global__ __launch_bounds__(256, 2) void xp_gemm_kernel()
{
    extern __shared__ __align__(16) uint32_t smp[];
    const int t = threadIdx.x;
    const int lane = t & 31, wid = t >> 5;
    const int wm = wid & 3, wn = wid >> 2;
    const size_t bm = (size_t)blockIdx.y * 128;
    const int bn = blockIdx.x * 128;

    float acc[2][8][4];
    #pragma unroll
    for (int i = 0; i < 2; i++)
        #pragma unroll
        for (int j = 0; j < 8; j++)
            #pragma unroll
            for (int k = 0; k < 4; k++) acc[i][j][k] = 0.f;

    gemm_hilo_core(smp, h3T_hi_g, h3T_lo_g, bm,
                   protoT_hi_g, protoT_lo_g, bn, 512, acc, t);

    #pragma unroll
    for (int ms = 0; ms < 2; ms++)
        #pragma unroll
        for (int nt = 0; nt < 8; nt++) {
            size_t row0 = bm + wm * 32 + ms * 16 + (lane >> 2);
            int col0 = bn + wn * 64 + nt * 8 + 2 * (lane & 3);
            *(float2*)&xp_g[row0 * 512 + col0] =
                make_float2(acc[ms][nt][0], acc[ms][nt][1]);
            *(float2*)&xp_g[(row0 + 8) * 512 + col0] =
                make_float2(acc[ms][nt][2], acc[ms][nt][3]);
        }
}

// up GEMM: C[4096x6400] = z * wupPT, BN+relu epilogue, col n = pos*256+c
__global__ __launch_bounds__(256, 2) void up_gemm_kernel(
    const float* __restrict__ bup,
    const float* __restrict__ gup, const float* __restrict__ btup)
{
    extern __shared__ __align__(16) uint32_t smp[];
    const int t = threadIdx.x;
    const int lane = t & 31, wid = t >> 5;
    const int wm = wid & 3, wn = wid >> 2;
    const size_t bm = (size_t)blockIdx.y * 128;
    const int bn = blockIdx.x * 128;

    float acc[2][8][4];
    #pragma unroll
    for (int i = 0; i < 2; i++)
        #pragma unroll
        for (int j = 0; j < 8; j++)
            #pragma unroll
            for (int k = 0; k < 4; k++) acc[i][j][k] = 0.f;

    gemm_hilo_core(smp, z_hi_g, z_lo_g, bm,
                   wupPT_hi_g, wupPT_lo_g, bn, 6400, acc, t);

    const float rsc = rsqrtf(1.f + BEPS);
    #pragma unroll
    for (int ms = 0; ms < 2; ms++)
        #pragma unroll
        for (int nt = 0; nt < 8; nt++) {
            size_t row0 = bm + wm * 32 + ms * 16 + (lane >> 2);
            int col0 = bn + wn * 64 + nt * 8 + 2 * (lane & 3);
            int c0 = col0 & 255, c1 = (col0 + 1) & 255;
            float s0 = gup[c0] * rsc, s1 = gup[c1] * rsc;
            float bi0 = bup[c0] * s0 + btup[c0];
            float bi1 = bup[c1] * s1 + btup[c1];
            *(float2*)&up2_g[row0 * 6400 + col0] =
                make_float2(fmaxf(acc[ms][nt][0] * s0 + bi0, 0.f),
                            fmaxf(acc[ms][nt][1] * s1 + bi1, 0.f));
            *(float2*)&up2_g[(row0 + 8) * 6400 + col0] =
                make_float2(fmaxf(acc[ms][nt][2] * s0 + bi0, 0.f),
                            fmaxf(acc[ms][nt][3] * s1 + bi1, 0.f));
        }
}

// ---------------------------------------------------------------------------
// g GEMM (mma.sync 3xTF32, in-loop cvt): G[102400x144] = up2 * wd1
// ---------------------------------------------------------------------------
#define AS_STRIDE 36
#define GBS_STRIDE 152
__global__ __launch_bounds__(512, 1) void g_gemm_kernel(const float* __restrict__ wd1)
{
    __shared__ float As[128 * AS_STRIDE];
    __shared__ float Bs[32 * GBS_STRIDE];

    const int t = threadIdx.x;
    const int lane = t & 31, wid = t >> 5;
    const int wm = wid & 7, wn = wid >> 3;
    const int bm = blockIdx.x * 128;

    float acc[9][4];
    #pragma unroll
    for (int j = 0; j < 9; j++)
        #pragma unroll
        for (int k = 0; k < 4; k++) acc[j][k] = 0.f;

    const int ar = t >> 2, ak = (t & 3) * 8;

    for (int k0 = 0; k0 < 256; k0 += 32) {
        const float* asrc = &up2_g[(size_t)(bm + ar) * 256 + k0 + ak];
        float4 av0 = *(const float4*)asrc;
        float4 av1 = *(const float4*)(asrc + 4);
        float bvals[9];
        #pragma unroll
        for (int j = 0; j < 9; j++) {
            int i = t + j * 512;
            int row = i / 144, col = i - row * 144;
            bvals[j] = wd1[(size_t)(k0 + row) * 144 + col];
        }
        __syncthreads();
        *(float4*)&As[ar * AS_STRIDE + ak]     = av0;
        *(float4*)&As[ar * AS_STRIDE + ak + 4] = av1;
        #pragma unroll
        for (int j = 0; j < 9; j++) {
            int i = t + j * 512;
            int row = i / 144, col = i - row * 144;
            Bs[row * GBS_STRIDE + col] = bvals[j];
        }
        __syncthreads();

        #pragma unroll
        for (int ks = 0; ks < 4; ks++) {
            const int col = ks * 8 + (lane & 3);
            uint32_t ah[4], al[4];
            {
                int mb = wm * 16 + (lane >> 2);
                float x0 = As[mb * AS_STRIDE + col];
                float x1 = As[(mb + 8) * AS_STRIDE + col];
                float x2 = As[mb * AS_STRIDE + col + 4];
                float x3 = As[(mb + 8) * AS_STRIDE + col + 4];
                cvt_hilo(x0, ah[0], al[0]);
                cvt_hilo(x1, ah[1], al[1]);
                cvt_hilo(x2, ah[2], al[2]);
                cvt_hilo(x3, ah[3], al[3]);
            }
            const int row = ks * 8 + (lane & 3);
            #pragma unroll
            for (int nt = 0; nt < 9; nt++) {
                int nb = wn * 72 + nt * 8 + (lane >> 2);
                float y0 = Bs[row * GBS_STRIDE + nb];
                float y1 = Bs[(row + 4) * GBS_STRIDE + nb];
                uint32_t bh[2], bl[2];
                cvt_hilo(y0, bh[0], bl[0]);
                cvt_hilo(y1, bh[1], bl[1]);
                mma_tf32(acc[nt], ah, bh);
                mma_tf32(acc[nt], ah, bl);
                mma_tf32(acc[nt], al, bh);
            }
        }
    }

    #pragma unroll
    for (int nt = 0; nt < 9; nt++) {
        int row0 = bm + wm * 16 + (lane >> 2);
        int col0 = wn * 72 + nt * 8 + 2 * (lane & 3);
        *(float2*)&G_g[(size_t)row0 * 144 + col0] = make_float2(acc[nt][0], acc[nt][1]);
        *(float2*)&G_g[(size_t)(row0 + 8) * 144 + col0] = make_float2(acc[nt][2], acc[nt][3]);
    }
}

// ---------------------------------------------------------------------------
// minsoftmax: distances from xp, min over pos, softmax -> w_g, minD out.
// ---------------------------------------------------------------------------
__global__ __launch_bounds__(512) void minsoftmax_kernel(float* __restrict__ out_minD)
{
    __shared__ float x2s[25];
    __shared__ float red[32];

    const int b = blockIdx.x;
    const int t = threadIdx.x;
    const int lane = t & 31, wid = t >> 5;

    for (int pos = wid; pos < 25; pos += 16) {
        const float* row = &h3T_g[((size_t)b * 25 + pos) * 256];
        float s = 0.f;
        #pragma unroll
        for (int j = 0; j < 8; j++) {
            float v = row[lane + 32 * j];
            s += v * v;
        }
        #pragma unroll
        for (int off = 16; off; off >>= 1) s += __shfl_xor_sync(0xffffffffu, s, off);
        if (!lane) x2s[pos] = s;
    }
    __syncthreads();

    const float pp = pp_g[t];
    float m = 3.0e38f;
    #pragma unroll 5
    for (int pos = 0; pos < 25; pos++) {
        float xv = xp_g[((size_t)b * 25 + pos) * 512 + t];
        float d = fmaxf(x2s[pos] - 2.f * xv + pp, 0.f);
        m = fminf(m, d);
    }
    out_minD[(size_t)b * 512 + t] = m;

    float a = -m;
    float v = a;
    #pragma unroll
    for (int off = 16; off; off >>= 1) v = fmaxf(v, __shfl_xor_sync(0xffffffffu, v, off));
    if (!lane) red[wid] = v;
    __syncthreads();
    if (t == 0) {
        float r = red[0];
        for (int i = 1; i < 16; i++) r = fmaxf(r, red[i]);
        red[16] = r;
    }
    __syncthreads();
    float amax = red[16];
    float e = expf(a - amax);
    float sv = e;
    #pragma unroll
    for (int off = 16; off; off >>= 1) sv += __shfl_xor_sync(0xffffffffu, sv, off);
    __syncthreads();
    if (!lane) red[wid] = sv;
    __syncthreads();
    if (t == 0) {
        float r = 0.f;
        for (int i = 0; i < 16; i++) r += red[i];
        red[16] = r;
    }
    __syncthreads();
    w_g[(size_t)b * 512 + t] = e * (1.f / red[16]);
}

// ---------------------------------------------------------------------------
// z GEMM (FFMA f32x2): z = w * proto; epilogue emits z hi/lo
// ---------------------------------------------------------------------------
__global__ __launch_bounds__(256) void z_gemm_kernel(const float* __restrict__ proto)
{
    __shared__ __align__(16) float As2[16][128];
    __shared__ __align__(16) float Bs2[16][64];
    const int bn = blockIdx.x * 64;
    const int bm = blockIdx.y * 128;
    const int t = threadIdx.x;
    const int tx = t & 15, ty = t >> 4;

    unsigned long long acc[4][4];
    #pragma unroll
    for (int i = 0; i < 4; i++)
        #pragma unroll
        for (int j = 0; j < 4; j++) acc[i][j] = 0ull;

    for (int k0 = 0; k0 < 512; k0 += 16) {
        #pragma unroll
        for (int s = t; s < 512; s += 256) {
            int r = s >> 2, kq = (s & 3) << 2;
            float4 v = *(const float4*)&w_g[(size_t)(bm + r) * 512 + k0 + kq];
            As2[kq + 0][r] = v.x; As2[kq + 1][r] = v.y;
            As2[kq + 2][r] = v.z; As2[kq + 3][r] = v.w;
        }
        {
            int kk = t >> 4, n4 = (t & 15) << 2;
            *(float4*)&Bs2[kk][n4] = *(const float4*)&proto[(size_t)(k0 + kk) * 256 + bn + n4];
        }
        __syncthreads();
        #pragma unroll
        for (int kk = 0; kk < 16; kk++) {
            ulonglong2 a01 = *(const ulonglong2*)&As2[kk][ty * 8];
            ulonglong2 a23 = *(const ulonglong2*)&As2[kk][ty * 8 + 4];
            float4 bv = *(const float4*)&Bs2[kk][tx * 4];
            unsigned long long bd0 = pack2(bv.x, bv.x), bd1 = pack2(bv.y, bv.y);
            unsigned long long bd2 = pack2(bv.z, bv.z), bd3 = pack2(bv.w, bv.w);
            acc[0][0] = ffma2(a01.x, bd0, acc[0][0]); acc[0][1] = ffma2(a01.x, bd1, acc[0][1]);
            acc[0][2] = ffma2(a01.x, bd2, acc[0][2]); acc[0][3] = ffma2(a01.x, bd3, acc[0][3]);
            acc[1][0] = ffma2(a01.y, bd0, acc[1][0]); acc[1][1] = ffma2(a01.y, bd1, acc[1][1]);
            acc[1][2] = ffma2(a01.y, bd2, acc[1][2]); acc[1][3] = ffma2(a01.y, bd3, acc[1][3]);
            acc[2][0] = ffma2(a23.x, bd0, acc[2][0]); acc[2][1] = ffma2(a23.x, bd1, acc[2][1]);
            acc[2][2] = ffma2(a23.x, bd2, acc[2][2]); acc[2][3] = ffma2(a23.x, bd3, acc[2][3]);
            acc[3][0] = ffma2(a23.y, bd0, acc[3][0]); acc[3][1] = ffma2(a23.y, bd1, acc[3][1]);
            acc[3][2] = ffma2(a23.y, bd2, acc[3][2]); acc[3][3] = ffma2(a23.y, bd3, acc[3][3]);
        }
        __syncthreads();
    }

    #pragma unroll
    for (int mp = 0; mp < 4; mp++) {
        int m0 = bm + ty * 8 + mp * 2;
        float2 f0 = unpack2(acc[mp][0]), f1 = unpack2(acc[mp][1]);
        float2 f2 = unpack2(acc[mp][2]), f3 = unpack2(acc[mp][3]);
        float rows[2][4] = {{f0.x, f1.x, f2.x, f3.x}, {f0.y, f1.y, f2.y, f3.y}};
        #pragma unroll
        for (int rr = 0; rr < 2; rr++) {
            uint4 hi, lo;
            cvt_hilo(rows[rr][0], hi.x, lo.x);
            cvt_hilo(rows[rr][1], hi.y, lo.y);
            cvt_hilo(rows[rr][2], hi.z, lo.z);
            cvt_hilo(rows[rr][3], hi.w, lo.w);
            size_t idx = (size_t)(m0 + rr) * 256 + bn + tx * 4;
            *(uint4*)&z_hi_g[idx] = hi;
            *(uint4*)&z_lo_g[idx] = lo;
        }
    }
}

// ---------------------------------------------------------------------------
// dec2: d1 = scatter(G)+BN+relu, then d2, d3. 2 images per block.
// ---------------------------------------------------------------------------
__global__ __launch_bounds__(256) void dec2_kernel(
    const float* __restrict__ bd1,
    const float* __restrict__ gd1, const float* __restrict__ btd1,
    const float* __restrict__ wd2, const float* __restrict__ bd2,
    const float* __restrict__ gd2, const float* __restrict__ btd2,
    const float* __restrict__ wd3, const float* __restrict__ bd3,
    float* __restrict__ out)
{
    extern __shared__ float sm[];
    float* Gs   = sm;                 // 2 * 3600
    float* d1s  = Gs + 7200;          // 2 * 784
    float* d2s  = d1s + 1568;         // 2 * 1568
    float* wd2s = d2s + 3136;         // 1152
    float* wd3s = wd2s + 1152;        // 72

    const int t = threadIdx.x;
    const int b0 = blockIdx.x * 2;
    const float rs = rsqrtf(1.f + BEPS);

    for (int i = t; i < 7200; i += 256) Gs[i] = G_g[(size_t)b0 * 3600 + i];
    for (int i = t; i < 1152; i += 256) wd2s[i] = wd2[i];
    if (t < 72) wd3s[t] = wd3[t];
    __syncthreads();

    for (int idx = t; idx < 1568; idx += 256) {
        int img = idx / 784, r = idx - img * 784;
        int o = r / 49, pos = r - o * 49;
        int oi = pos / 7, oj = pos % 7;
        int y0 = max(oi - 2, 0), y1 = min(oi, 4);
        int x0 = max(oj - 2, 0), x1 = min(oj, 4);
        float sum = 0.f;
        const float* Gb = &Gs[img * 3600];
        for (int y = y0; y <= y1; y++) {
            int ki = oi - y;
            for (int xx = x0; xx <= x1; xx++) {
                int kj = oj - xx;
                sum += Gb[(y * 5 + xx) * 144 + o * 9 + ki * 3 + kj];
            }
        }
        float s = gd1[o] * rs;
        d1s[img * 784 + o * 49 + pos] = fmaxf((sum + bd1[o]) * s + btd1[o], 0.f);
    }
    __syncthreads();

    if (t < 196) {
        float acc2[2][8];
        #pragma unroll
        for (int a = 0; a < 2; a++)
            #pragma unroll
            for (int o = 0; o < 8; o++) acc2[a][o] = 0.f;
        int i = t / 14, j = t % 14;
        int ylo = i / 2, yhi = min((i + 1) / 2, 6);
        int xlo = j / 2, xhi = min((j + 1) / 2, 6);
        for (int c = 0; c < 16; c++) {
            for (int y = ylo; y <= yhi; y++) {
                int ki = i - 2 * y + 1;
                for (int xx = xlo; xx <= xhi; xx++) {
                    int kj = j - 2 * xx + 1;
                    float u0 = d1s[0 * 784 + c * 49 + y * 7 + xx];
                    float u1 = d1s[1 * 784 + c * 49 + y * 7 + xx];
                    #pragma unroll
                    for (int o = 0; o < 8; o++) {
                        float wv = wd2s[((c * 8 + o) * 3 + ki) * 3 + kj];
                        acc2[0][o] += u0 * wv;
                        acc2[1][o] += u1 * wv;
                    }
                }
            }
        }
        #pragma unroll
        for (int o = 0; o < 8; o++) {
            float s = gd2[o] * rs;
            float bias = bd2[o] * s + btd2[o];
            #pragma unroll
            for (int a = 0; a < 2; a++)
                d2s[a * 1568 + o * 196 + t] = fmaxf(acc2[a][o] * s + bias, 0.f);
        }
    }
    __syncthreads();

    const float bb3 = bd3[0];
    for (int idx = t; idx < 1568; idx += 256) {
        int a = idx / 784, p = idx - a * 784, i = p / 28, j = p % 28;
        int ylo = i / 2, yhi = min((i + 1) / 2, 13);
        int xlo = j / 2, xhi = min((j + 1) / 2, 13);
        float acc3 = bb3;
        for (int c = 0; c < 8; c++) {
            for (int y = ylo; y <= yhi; y++) {
                int ki = i - 2 * y + 1;
                for (int xx = xlo; xx <= xhi; xx++) {
                    int kj = j - 2 * xx + 1;
                    acc3 += d2s[a * 1568 + c * 196 + y * 14 + xx] * wd3s[c * 9 + ki * 3 + kj];
                }
            }
        }
        out[(size_t)(b0 + a) * 784 + p] = 1.f / (1.f + expf(-acc3));
    }
}

// ---------------------------------------------------------------------------
extern "C" void kernel_launch(void* const* d_in, const int* in_sizes, int n_in,
                              void* d_out, int out_size)
{
    const float* x     = (const float*)d_in[0];
    const float* w1    = (const float*)d_in[1];
    const float* b1    = (const float*)d_in[2];
    const float* w2    = (const float*)d_in[3];
    const float* b2    = (const float*)d_in[4];
    const float* g2    = (const float*)d_in[5];
    const float* bt2   = (const float*)d_in[6];
    const float* w3    = (const float*)d_in[7];
    const float* b3    = (const float*)d_in[8];
    const float* proto = (const float*)d_in[9];
    const float* wup   = (const float*)d_in[10];
    const float* bup   = (const float*)d_in[11];
    const float* gup   = (const float*)d_in[12];
    const float* btup  = (const float*)d_in[13];
    const float* wd1   = (const float*)d_in[14];
    const float* bd1   = (const float*)d_in[15];
    const float* gd1   = (const float*)d_in[16];
    const float* btd1  = (const float*)d_in[17];
    const float* wd2   = (const float*)d_in[18];
    const float* bd2   = (const float*)d_in[19];
    const float* gd2   = (const float*)d_in[20];
    const float* btd2  = (const float*)d_in[21];
    const float* wd3   = (const float*)d_in[22];
    const float* bd3   = (const float*)d_in[23];

    float* out  = (float*)d_out;                 // (4096,1,28,28)
    float* minD = out + (size_t)NB * 784;        // (4096,512)

    prep_kernel<<<256, 256>>>(proto, w3, wup);
    enc12_kernel<<<NB, 128>>>(x, w1, b1, w2, b2, g2, bt2);
    conv3_kernel<<<NB, 256>>>(b3);

    cudaFuncSetAttribute(xp_gemm_kernel, cudaFuncAttributeMaxDynamicSharedMemorySize, PIPE_SMEM);
    dim3 gx(512 / 128, (NB * 25) / 128);         // (4, 800)
    xp_gemm_kernel<<<gx, 256, PIPE_SMEM>>>();

    minsoftmax_kernel<<<NB, 512>>>(minD);

    dim3 gz(256 / 64, NB / 128);
    z_gemm_kernel<<<gz, 256>>>(proto);

    cudaFuncSetAttribute(up_gemm_kernel, cudaFuncAttributeMaxDynamicSharedMemorySize, PIPE_SMEM);
    dim3 gu(6400 / 128, NB / 128);               // (50, 32)
    up_gemm_kernel<<<gu, 256, PIPE_SMEM>>>(bup, gup, btup);

    g_gemm_kernel<<<(NB * 25) / 128, 512>>>(wd1);   // 800 blocks

    size_t smem2 = (size_t)(7200 + 1568 + 3136 + 1152 + 72) * sizeof(float); // 52,512 B
    cudaFuncSetAttribute(dec2_kernel, cudaFuncAttributeMaxDynamicSharedMemorySize, (int)smem2);
    dec2_kernel<<<NB / 2, 256, smem2>>>(bd1, gd1, btd1,
                                        wd2, bd2, gd2, btd2,
                                        wd3, bd3, out);
}

// round 12
// speedup vs baseline: 1.0055x; 1.0055x over previous
#include <cuda_runtime.h>
#include <math.h>
#include <stdint.h>

#define BEPS 1e-5f
#define NB 4096
#define INFBITS 0x7F800000u

// ---------------- scratch (allocation-free) ----------------
__device__ float h2_g[NB * 784];
__device__ float h3T_g[(size_t)NB * 25 * 256];        // [(b*25+pos)][d]
__device__ uint32_t h3T_hi_g[(size_t)NB * 25 * 256];  // tf32 hi
__device__ uint32_t h3T_lo_g[(size_t)NB * 25 * 256];  // tf32 lo
__device__ float x2_g[(size_t)NB * 25];               // per-row squared norm
__device__ float w_g[NB * 512];
__device__ uint32_t z_hi_g[NB * 256];
__device__ uint32_t z_lo_g[NB * 256];
__device__ float up2_g[(size_t)NB * 6400];            // [(b*25+pos)][c]
__device__ float G_g[(size_t)NB * 25 * 144];          // [(b*25+pos)][o*9+tap]
__device__ float protoT_g[256 * 512];                 // [d][p] raw (z_gemm B)
__device__ uint32_t protoT_hi_g[256 * 512];           // [k][n] tf32 hi
__device__ uint32_t protoT_lo_g[256 * 512];
__device__ uint32_t wupPT_hi_g[256 * 6400];           // [k][pos*256+c]
__device__ uint32_t wupPT_lo_g[256 * 6400];
__device__ float pp_g[512];                           // sum_d proto^2
__device__ float w3t_g[256 * 144];                    // [(c*9+tap)][oc]

// ---------------- packed fp32x2 helpers ----------------
static __device__ __forceinline__ unsigned long long ffma2(
    unsigned long long a, unsigned long long b, unsigned long long c) {
    unsigned long long d;
    asm("fma.rn.f32x2 %0, %1, %2, %3;" : "=l"(d) : "l"(a), "l"(b), "l"(c));
    return d;
}
static __device__ __forceinline__ unsigned long long pack2(float x, float y) {
    unsigned long long r;
    asm("mov.b64 %0, {%1, %2};" : "=l"(r) : "f"(x), "f"(y));
    return r;
}
static __device__ __forceinline__ float2 unpack2(unsigned long long v) {
    float2 r;
    asm("mov.b64 {%0, %1}, %2;" : "=f"(r.x), "=f"(r.y) : "l"(v));
    return r;
}

// ---------------- tf32 helpers ----------------
static __device__ __forceinline__ void cvt_hilo(float x, uint32_t& hi, uint32_t& lo) {
    uint32_t h;
    asm("cvt.rna.tf32.f32 %0, %1;" : "=r"(h) : "f"(x));
    float hf = __uint_as_float(h);
    float l = x - hf;
    asm("cvt.rna.tf32.f32 %0, %1;" : "=r"(lo) : "f"(l));
    hi = h;
}
static __device__ __forceinline__ void mma_tf32(float* c, const uint32_t* a, const uint32_t* b) {
    asm volatile(
        "mma.sync.aligned.m16n8k8.row.col.f32.tf32.tf32.f32 "
        "{%0,%1,%2,%3}, {%4,%5,%6,%7}, {%8,%9}, {%0,%1,%2,%3};"
        : "+f"(c[0]), "+f"(c[1]), "+f"(c[2]), "+f"(c[3])
        : "r"(a[0]), "r"(a[1]), "r"(a[2]), "r"(a[3]), "r"(b[0]), "r"(b[1]));
}

// ---------------- cp.async helpers ----------------
static __device__ __forceinline__ uint32_t smem_u32(const void* p) {
    uint32_t a;
    asm("{ .reg .u64 t; cvta.to.shared.u64 t, %1; cvt.u32.u64 %0, t; }" : "=r"(a) : "l"(p));
    return a;
}
#define CPASYNC16(dst, src) \
    asm volatile("cp.async.cg.shared.global [%0], [%1], 16;" :: "r"(dst), "l"(src) : "memory")
#define CPCOMMIT() asm volatile("cp.async.commit_group;" ::: "memory")
#define CPWAIT1() asm volatile("cp.async.wait_group 1;" ::: "memory")
#define CPWAIT0() asm volatile("cp.async.wait_group 0;" ::: "memory")

// ---------------------------------------------------------------------------
// prep: hi/lo splits + transposes + proto norms
// ---------------------------------------------------------------------------
__global__ void prep_kernel(const float* __restrict__ proto,
                            const float* __restrict__ w3,
                            const float* __restrict__ wup)
{
    int stride = gridDim.x * blockDim.x;
    int tid = blockIdx.x * blockDim.x + threadIdx.x;
    for (int i = tid; i < 512 * 256; i += stride) {
        int d = i >> 9, p = i & 511;
        float v = proto[p * 256 + d];
        protoT_g[i] = v;
        uint32_t hi, lo;
        cvt_hilo(v, hi, lo);
        protoT_hi_g[i] = hi;
        protoT_lo_g[i] = lo;
    }
    for (int p = tid; p < 512; p += stride) {
        float s = 0.f;
        for (int d = 0; d < 256; d++) {
            float v = proto[p * 256 + d];
            s += v * v;
        }
        pp_g[p] = s;
    }
    for (int i = tid; i < 256 * 144; i += stride) {
        int o = i & 255, ct = i >> 8;
        int c = ct / 9, tap = ct - c * 9;
        w3t_g[i] = w3[o * 144 + c * 9 + tap];
    }
    for (int i = tid; i < 256 * 6400; i += stride) {
        int k = i / 6400, rr = i % 6400;
        int pos = rr >> 8, c = rr & 255;
        float v = wup[(size_t)k * 6400 + c * 25 + pos];
        uint32_t hi, lo;
        cvt_hilo(v, hi, lo);
        wupPT_hi_g[i] = hi;
        wupPT_lo_g[i] = lo;
    }
}

// ---------------------------------------------------------------------------
// init minD to +inf
// ---------------------------------------------------------------------------
__global__ __launch_bounds__(512) void init_mind_kernel(float* __restrict__ minD)
{
    minD[(size_t)blockIdx.x * 512 + threadIdx.x] = __uint_as_float(INFBITS);
}

// ---------------------------------------------------------------------------
// enc12: conv1 + conv2, one block per image
// ---------------------------------------------------------------------------
__global__ __launch_bounds__(128) void enc12_kernel(
    const float* __restrict__ x,
    const float* __restrict__ w1, const float* __restrict__ b1,
    const float* __restrict__ w2, const float* __restrict__ b2,
    const float* __restrict__ g2, const float* __restrict__ bt2)
{
    __shared__ float xs[784];
    __shared__ float h1s[8 * 196];
    const int b = blockIdx.x;
    const int t = threadIdx.x;

    const float* xb = x + b * 784;
    for (int i = t; i < 784; i += 128) xs[i] = xb[i];
    __syncthreads();

    for (int idx = t; idx < 1568; idx += 128) {
        int o = idx / 196, r = idx % 196, i = r / 14, j = r % 14;
        float acc = b1[o];
        #pragma unroll
        for (int ky = 0; ky < 3; ky++) {
            int y = 2 * i - 1 + ky;
            if ((unsigned)y >= 28u) continue;
            #pragma unroll
            for (int kx = 0; kx < 3; kx++) {
                int xx = 2 * j - 1 + kx;
                if ((unsigned)xx >= 28u) continue;
                acc += xs[y * 28 + xx] * w1[o * 9 + ky * 3 + kx];
            }
        }
        h1s[idx] = fmaxf(acc, 0.f);
    }
    __syncthreads();

    const float rs = rsqrtf(1.f + BEPS);
    for (int idx = t; idx < 784; idx += 128) {
        int o = idx / 49, r = idx % 49, i = r / 7, j = r % 7;
        float acc = 0.f;
        for (int c = 0; c < 8; c++) {
            #pragma unroll
            for (int ky = 0; ky < 3; ky++) {
                int y = 2 * i - 1 + ky;
                if ((unsigned)y >= 14u) continue;
                #pragma unroll
                for (int kx = 0; kx < 3; kx++) {
                    int xx = 2 * j - 1 + kx;
                    if ((unsigned)xx >= 14u) continue;
                    acc += h1s[c * 196 + y * 14 + xx] * w2[((o * 8 + c) * 3 + ky) * 3 + kx];
                }
            }
        }
        float s = g2[o] * rs;
        h2_g[b * 784 + idx] = fmaxf((acc + b2[o]) * s + bt2[o], 0.f);
    }
}

// ---------------------------------------------------------------------------
// conv3: 16->256 k3 s1 p0, 7->5; writes h3T raw + tf32 hi/lo
// ---------------------------------------------------------------------------
__global__ __launch_bounds__(256, 2) void conv3_kernel(const float* __restrict__ b3)
{
    __shared__ float h2s[784];
    const int b = blockIdx.x;
    const int t = threadIdx.x;

    for (int i = t; i < 784; i += 256) h2s[i] = h2_g[b * 784 + i];
    __syncthreads();

    float acc[25];
    #pragma unroll
    for (int p = 0; p < 25; p++) acc[p] = 0.f;

    for (int c = 0; c < 16; c++) {
        float w[9];
        #pragma unroll
        for (int tap = 0; tap < 9; tap++) w[tap] = w3t_g[(c * 9 + tap) * 256 + t];
        float h[49];
        #pragma unroll
        for (int i = 0; i < 49; i++) h[i] = h2s[c * 49 + i];
        #pragma unroll
        for (int ky = 0; ky < 3; ky++)
            #pragma unroll
            for (int kx = 0; kx < 3; kx++) {
                float wv = w[ky * 3 + kx];
                #pragma unroll
                for (int i = 0; i < 5; i++)
                    #pragma unroll
                    for (int j = 0; j < 5; j++)
                        acc[i * 5 + j] += wv * h[(i + ky) * 7 + (j + kx)];
            }
    }
    float bb = b3[t];
    #pragma unroll
    for (int p = 0; p < 25; p++) {
        float v = fmaxf(acc[p] + bb, 0.f);
        size_t idx = ((size_t)b * 25 + p) * 256 + t;
        h3T_g[idx] = v;
        uint32_t hi, lo;
        cvt_hilo(v, hi, lo);
        h3T_hi_g[idx] = hi;
        h3T_lo_g[idx] = lo;
    }
}

// ---------------------------------------------------------------------------
// x2: per-row squared norm of h3T (warp per row)
// ---------------------------------------------------------------------------
__global__ __launch_bounds__(256) void x2_kernel()
{
    const int wid = threadIdx.x >> 5, lane = threadIdx.x & 31;
    const size_t row = (size_t)blockIdx.x * 8 + wid;
    const float* r = &h3T_g[row * 256];
    float s = 0.f;
    #pragma unroll
    for (int j = 0; j < 8; j++) {
        float v = r[lane + 32 * j];
        s += v * v;
    }
    #pragma unroll
    for (int off = 16; off; off >>= 1) s += __shfl_xor_sync(0xffffffffu, s, off);
    if (!lane) x2_g[row] = s;
}

// ===========================================================================
// 3xTF32 GEMM cores with PRE-SPLIT hi/lo operands — no cvt in the mainloop.
// Block 128x128, 8 warps (4m x 2n), warp tile 32x64, k-chunk 16, 2 stages.
// ===========================================================================
#define ASTR 20
#define BSTR 136
#define ASTG16 (128 * ASTR)
#define BSTG16 (16 * BSTR)
#define OFF_AL (2 * ASTG16)
#define OFF_BH (4 * ASTG16)
#define OFF_BL (4 * ASTG16 + 2 * BSTG16)
#define PIPE_SMEM ((4 * ASTG16 + 4 * BSTG16) * 4)   // 75,776 bytes

static __device__ __forceinline__ void gemm_hilo_core(
    uint32_t* smp,
    const uint32_t* __restrict__ gAh, const uint32_t* __restrict__ gAl, size_t arow0,
    const uint32_t* __restrict__ gBh, const uint32_t* __restrict__ gBl, size_t bcol0,
    int ldb, float acc[2][8][4], int t)
{
    const int lane = t & 31, wid = t >> 5;
    const int wm = wid & 3, wn = wid >> 2;

    const int ar = t >> 1, ak = (t & 1) * 8;
    const int br = t >> 4, bn8 = (t & 15) * 8;
    const uint32_t smb = smem_u32(smp);
    const uint32_t sAh = smb + (uint32_t)(ar * ASTR + ak) * 4;
    const uint32_t sAl = sAh + OFF_AL * 4;
    const uint32_t sBh = smb + (uint32_t)(OFF_BH + br * BSTR + bn8) * 4;
    const uint32_t sBl = sBh + 2 * BSTG16 * 4;
    const uint32_t* gA_h = gAh + (arow0 + ar) * 256 + ak;
    const uint32_t* gA_l = gAl + (arow0 + ar) * 256 + ak;
    const uint32_t* gB_h = gBh + (size_t)br * ldb + bcol0 + bn8;
    const uint32_t* gB_l = gBl + (size_t)br * ldb + bcol0 + bn8;

    CPASYNC16(sAh, gA_h);          CPASYNC16(sAh + 16, gA_h + 4);
    CPASYNC16(sAl, gA_l);          CPASYNC16(sAl + 16, gA_l + 4);
    CPASYNC16(sBh, gB_h);          CPASYNC16(sBh + 16, gB_h + 4);
    CPASYNC16(sBl, gB_l);          CPASYNC16(sBl + 16, gB_l + 4);
    CPCOMMIT();

    for (int c = 0; c < 16; c++) {
        if (c < 15) {
            const int k0 = (c + 1) * 16;
            const uint32_t st = (uint32_t)((c + 1) & 1);
            uint32_t dAh = sAh + st * ASTG16 * 4;
            uint32_t dAl = sAl + st * ASTG16 * 4;
            uint32_t dBh = sBh + st * BSTG16 * 4;
            uint32_t dBl = sBl + st * BSTG16 * 4;
            CPASYNC16(dAh, gA_h + k0);      CPASYNC16(dAh + 16, gA_h + k0 + 4);
            CPASYNC16(dAl, gA_l + k0);      CPASYNC16(dAl + 16, gA_l + k0 + 4);
            CPASYNC16(dBh, gB_h + (size_t)k0 * ldb);
            CPASYNC16(dBh + 16, gB_h + (size_t)k0 * ldb + 4);
            CPASYNC16(dBl, gB_l + (size_t)k0 * ldb);
            CPASYNC16(dBl + 16, gB_l + (size_t)k0 * ldb + 4);
            CPCOMMIT();
            CPWAIT1();
        } else {
            CPWAIT0();
        }
        __syncthreads();

        const uint32_t st = (uint32_t)(c & 1);
        const uint32_t* Ah = smp + st * ASTG16;
        const uint32_t* Al = Ah + OFF_AL;
        const uint32_t* Bh = smp + OFF_BH + st * BSTG16;
        const uint32_t* Bl = Bh + 2 * BSTG16;

        #pragma unroll
        for (int ks = 0; ks < 2; ks++) {
            const int col = ks * 8 + (lane & 3);
            uint32_t ah[2][4], al[2][4];
            #pragma unroll
            for (int ms = 0; ms < 2; ms++) {
                int mb = wm * 32 + ms * 16 + (lane >> 2);
                ah[ms][0] = Ah[mb * ASTR + col];
                ah[ms][1] = Ah[(mb + 8) * ASTR + col];
                ah[ms][2] = Ah[mb * ASTR + col + 4];
                ah[ms][3] = Ah[(mb + 8) * ASTR + col + 4];
                al[ms][0] = Al[mb * ASTR + col];
                al[ms][1] = Al[(mb + 8) * ASTR + col];
                al[ms][2] = Al[mb * ASTR + col + 4];
                al[ms][3] = Al[(mb + 8) * ASTR + col + 4];
            }
            const int row = ks * 8 + (lane & 3);
            #pragma unroll
            for (int nt = 0; nt < 8; nt++) {
                int nb = wn * 64 + nt * 8 + (lane >> 2);
                uint32_t bh[2], bl[2];
                bh[0] = Bh[row * BSTR + nb];
                bh[1] = Bh[(row + 4) * BSTR + nb];
                bl[0] = Bl[row * BSTR + nb];
                bl[1] = Bl[(row + 4) * BSTR + nb];
                #pragma unroll
                for (int ms = 0; ms < 2; ms++) {
                    mma_tf32(acc[ms][nt], ah[ms], bh);
                    mma_tf32(acc[ms][nt], ah[ms], bl);
                    mma_tf32(acc[ms][nt], al[ms], bh);
                }
            }
        }
        __syncthreads();
    }
}

// xp GEMM + fused distance/min: minD[b][p] = min_pos relu(x2 - 2*xp + pp)
__global__ __launch_bounds__(256, 2) void xp_gemm_kernel(float* __restrict__ minD)
{
    extern __shared__ __align__(16) uint32_t smp[];
    const int t = threadIdx.x;
    const int lane = t & 31, wid = t >> 5;
    const int wm = wid & 3, wn = wid >> 2;
    const size_t bm = (size_t)blockIdx.y * 128;
    const int bn = blockIdx.x * 128;

    float acc[2][8][4];
    #pragma unroll
    for (int i = 0; i < 2; i++)
        #pragma unroll
        for (int j = 0; j < 8; j++)
            #pragma unroll
            for (int k = 0; k < 4; k++) acc[i][j][k] = 0.f;

    gemm_hilo_core(smp, h3T_hi_g, h3T_lo_g, bm,
                   protoT_hi_g, protoT_lo_g, bn, 512, acc, t);

    // ---- epilogue: distances + min over pos ----
    unsigned* minred = (unsigned*)smp;           // [8][128]
    float* pps = (float*)(smp + 1024);           // [128]
    for (int i = t; i < 1024; i += 256) minred[i] = INFBITS;
    if (t < 128) pps[t] = pp_g[bn + t];
    __syncthreads();

    const int img0 = (int)(bm / 25);

    float x2v[2][2];
    #pragma unroll
    for (int ms = 0; ms < 2; ms++) {
        int r0 = wm * 32 + ms * 16 + (lane >> 2);
        x2v[ms][0] = x2_g[bm + r0];
        x2v[ms][1] = x2_g[bm + r0 + 8];
    }

    #pragma unroll
    for (int ms = 0; ms < 2; ms++) {
        int r0 = wm * 32 + ms * 16 + (lane >> 2);
        int slot0 = (int)((bm + r0) / 25) - img0;
        int slot1 = (int)((bm + r0 + 8) / 25) - img0;
        #pragma unroll
        for (int nt = 0; nt < 8; nt++) {
            int ncol = wn * 64 + nt * 8 + 2 * (lane & 3);
            float p0 = pps[ncol], p1 = pps[ncol + 1];
            float d00 = fmaxf(x2v[ms][0] - 2.f * acc[ms][nt][0] + p0, 0.f);
            float d01 = fmaxf(x2v[ms][0] - 2.f * acc[ms][nt][1] + p1, 0.f);
            float d10 = fmaxf(x2v[ms][1] - 2.f * acc[ms][nt][2] + p0, 0.f);
            float d11 = fmaxf(x2v[ms][1] - 2.f * acc[ms][nt][3] + p1, 0.f);
            atomicMin(&minred[slot0 * 128 + ncol], __float_as_uint(d00));
            atomicMin(&minred[slot0 * 128 + ncol + 1], __float_as_uint(d01));
            atomicMin(&minred[slot1 * 128 + ncol], __float_as_uint(d10));
            atomicMin(&minred[slot1 * 128 + ncol + 1], __float_as_uint(d11));
        }
    }
    __syncthreads();

    for (int i = t; i < 1024; i += 256) {
        unsigned v = minred[i];
        if (v != INFBITS) {
            int slot = i >> 7, col = i & 127;
            atomicMin((unsigned*)&minD[(size_t)(img0 + slot) * 512 + bn + col], v);
        }
    }
}

// up GEMM: C[4096x6400] = z * wupPT, BN+relu epilogue, col n = pos*256+c
__global__ __launch_bounds__(256, 2) void up_gemm_kernel(
    const float* __restrict__ bup,
    const float* __restrict__ gup, const float* __restrict__ btup)
{
    extern __shared__ __align__(16) uint32_t smp[];
    const int t = threadIdx.x;
    const int lane = t & 31, wid = t >> 5;
    const int wm = wid & 3, wn = wid >> 2;
    const size_t bm = (size_t)blockIdx.y * 128;
    const int bn = blockIdx.x * 128;

    float acc[2][8][4];
    #pragma unroll
    for (int i = 0; i < 2; i++)
        #pragma unroll
        for (int j = 0; j < 8; j++)
            #pragma unroll
            for (int k = 0; k < 4; k++) acc[i][j][k] = 0.f;

    gemm_hilo_core(smp, z_hi_g, z_lo_g, bm,
                   wupPT_hi_g, wupPT_lo_g, bn, 6400, acc, t);

    const float rsc = rsqrtf(1.f + BEPS);
    #pragma unroll
    for (int ms = 0; ms < 2; ms++)
        #pragma unroll
        for (int nt = 0; nt < 8; nt++) {
            size_t row0 = bm + wm * 32 + ms * 16 + (lane >> 2);
            int col0 = bn + wn * 64 + nt * 8 + 2 * (lane & 3);
            int c0 = col0 & 255, c1 = (col0 + 1) & 255;
            float s0 = gup[c0] * rsc, s1 = gup[c1] * rsc;
            float bi0 = bup[c0] * s0 + btup[c0];
            float bi1 = bup[c1] * s1 + btup[c1];
            *(float2*)&up2_g[row0 * 6400 + col0] =
                make_float2(fmaxf(acc[ms][nt][0] * s0 + bi0, 0.f),
                            fmaxf(acc[ms][nt][1] * s1 + bi1, 0.f));
            *(float2*)&up2_g[(row0 + 8) * 6400 + col0] =
                make_float2(fmaxf(acc[ms][nt][2] * s0 + bi0, 0.f),
                            fmaxf(acc[ms][nt][3] * s1 + bi1, 0.f));
        }
}

// ---------------------------------------------------------------------------
// g GEMM (mma.sync 3xTF32, in-loop cvt): G[102400x144] = up2 * wd1
// ---------------------------------------------------------------------------
#define AS_STRIDE 36
#define GBS_STRIDE 152
__global__ __launch_bounds__(512, 1) void g_gemm_kernel(const float* __restrict__ wd1)
{
    __shared__ float As[128 * AS_STRIDE];
    __shared__ float Bs[32 * GBS_STRIDE];

    const int t = threadIdx.x;
    const int lane = t & 31, wid = t >> 5;
    const int wm = wid & 7, wn = wid >> 3;
    const int bm = blockIdx.x * 128;

    float acc[9][4];
    #pragma unroll
    for (int j = 0; j < 9; j++)
        #pragma unroll
        for (int k = 0; k < 4; k++) acc[j][k] = 0.f;

    const int ar = t >> 2, ak = (t & 3) * 8;

    for (int k0 = 0; k0 < 256; k0 += 32) {
        const float* asrc = &up2_g[(size_t)(bm + ar) * 256 + k0 + ak];
        float4 av0 = *(const float4*)asrc;
        float4 av1 = *(const float4*)(asrc + 4);
        float bvals[9];
        #pragma unroll
        for (int j = 0; j < 9; j++) {
            int i = t + j * 512;
            int row = i / 144, col = i - row * 144;
            bvals[j] = wd1[(size_t)(k0 + row) * 144 + col];
        }
        __syncthreads();
        *(float4*)&As[ar * AS_STRIDE + ak]     = av0;
        *(float4*)&As[ar * AS_STRIDE + ak + 4] = av1;
        #pragma unroll
        for (int j = 0; j < 9; j++) {
            int i = t + j * 512;
            int row = i / 144, col = i - row * 144;
            Bs[row * GBS_STRIDE + col] = bvals[j];
        }
        __syncthreads();

        #pragma unroll
        for (int ks = 0; ks < 4; ks++) {
            const int col = ks * 8 + (lane & 3);
            uint32_t ah[4], al[4];
            {
                int mb = wm * 16 + (lane >> 2);
                float x0 = As[mb * AS_STRIDE + col];
                float x1 = As[(mb + 8) * AS_STRIDE + col];
                float x2 = As[mb * AS_STRIDE + col + 4];
                float x3 = As[(mb + 8) * AS_STRIDE + col + 4];
                cvt_hilo(x0, ah[0], al[0]);
                cvt_hilo(x1, ah[1], al[1]);
                cvt_hilo(x2, ah[2], al[2]);
                cvt_hilo(x3, ah[3], al[3]);
            }
            const int row = ks * 8 + (lane & 3);
            #pragma unroll
            for (int nt = 0; nt < 9; nt++) {
                int nb = wn * 72 + nt * 8 + (lane >> 2);
                float y0 = Bs[row * GBS_STRIDE + nb];
                float y1 = Bs[(row + 4) * GBS_STRIDE + nb];
                uint32_t bh[2], bl[2];
                cvt_hilo(y0, bh[0], bl[0]);
                cvt_hilo(y1, bh[1], bl[1]);
                mma_tf32(acc[nt], ah, bh);
                mma_tf32(acc[nt], ah, bl);
                mma_tf32(acc[nt], al, bh);
            }
        }
    }

    #pragma unroll
    for (int nt = 0; nt < 9; nt++) {
        int row0 = bm + wm * 16 + (lane >> 2);
        int col0 = wn * 72 + nt * 8 + 2 * (lane & 3);
        *(float2*)&G_g[(size_t)row0 * 144 + col0] = make_float2(acc[nt][0], acc[nt][1]);
        *(float2*)&G_g[(size_t)(row0 + 8) * 144 + col0] = make_float2(acc[nt][2], acc[nt][3]);
    }
}

// ---------------------------------------------------------------------------
// softmax over minD -> w_g
// ---------------------------------------------------------------------------
__global__ __launch_bounds__(512) void softmax_kernel(const float* __restrict__ minD)
{
    __shared__ float red[32];
    const int b = blockIdx.x;
    const int t = threadIdx.x;
    const int lane = t & 31, wid = t >> 5;

    float m = minD[(size_t)b * 512 + t];
    float a = -m;
    float v = a;
    #pragma unroll
    for (int off = 16; off; off >>= 1) v = fmaxf(v, __shfl_xor_sync(0xffffffffu, v, off));
    if (!lane) red[wid] = v;
    __syncthreads();
    if (t == 0) {
        float r = red[0];
        for (int i = 1; i < 16; i++) r = fmaxf(r, red[i]);
        red[16] = r;
    }
    __syncthreads();
    float amax = red[16];
    float e = expf(a - amax);
    float sv = e;
    #pragma unroll
    for (int off = 16; off; off >>= 1) sv += __shfl_xor_sync(0xffffffffu, sv, off);
    __syncthreads();
    if (!lane) red[wid] = sv;
    __syncthreads();
    if (t == 0) {
        float r = 0.f;
        for (int i = 0; i < 16; i++) r += red[i];
        red[16] = r;
    }
    __syncthreads();
    w_g[(size_t)b * 512 + t] = e * (1.f / red[16]);
}

// ---------------------------------------------------------------------------
// z GEMM (FFMA f32x2): z = w * proto; epilogue emits z hi/lo
// ---------------------------------------------------------------------------
__global__ __launch_bounds__(256) void z_gemm_kernel(const float* __restrict__ proto)
{
    __shared__ __align__(16) float As2[16][128];
    __shared__ __align__(16) float Bs2[16][64];
    const int bn = blockIdx.x * 64;
    const int bm = blockIdx.y * 128;
    const int t = threadIdx.x;
    const int tx = t & 15, ty = t >> 4;

    unsigned long long acc[4][4];
    #pragma unroll
    for (int i = 0; i < 4; i++)
        #pragma unroll
        for (int j = 0; j < 4; j++) acc[i][j] = 0ull;

    for (int k0 = 0; k0 < 512; k0 += 16) {
        #pragma unroll
        for (int s = t; s < 512; s += 256) {
            int r = s >> 2, kq = (s & 3) << 2;
            float4 v = *(const float4*)&w_g[(size_t)(bm + r) * 512 + k0 + kq];
            As2[kq + 0][r] = v.x; As2[kq + 1][r] = v.y;
            As2[kq + 2][r] = v.z; As2[kq + 3][r] = v.w;
        }
        {
            int kk = t >> 4, n4 = (t & 15) << 2;
            *(float4*)&Bs2[kk][n4] = *(const float4*)&proto[(size_t)(k0 + kk) * 256 + bn + n4];
        }
        __syncthreads();
        #pragma unroll
        for (int kk = 0; kk < 16; kk++) {
            ulonglong2 a01 = *(const ulonglong2*)&As2[kk][ty * 8];
            ulonglong2 a23 = *(const ulonglong2*)&As2[kk][ty * 8 + 4];
            float4 bv = *(const float4*)&Bs2[kk][tx * 4];
            unsigned long long bd0 = pack2(bv.x, bv.x), bd1 = pack2(bv.y, bv.y);
            unsigned long long bd2 = pack2(bv.z, bv.z), bd3 = pack2(bv.w, bv.w);
            acc[0][0] = ffma2(a01.x, bd0, acc[0][0]); acc[0][1] = ffma2(a01.x, bd1, acc[0][1]);
            acc[0][2] = ffma2(a01.x, bd2, acc[0][2]); acc[0][3] = ffma2(a01.x, bd3, acc[0][3]);
            acc[1][0] = ffma2(a01.y, bd0, acc[1][0]); acc[1][1] = ffma2(a01.y, bd1, acc[1][1]);
            acc[1][2] = ffma2(a01.y, bd2, acc[1][2]); acc[1][3] = ffma2(a01.y, bd3, acc[1][3]);
            acc[2][0] = ffma2(a23.x, bd0, acc[2][0]); acc[2][1] = ffma2(a23.x, bd1, acc[2][1]);
            acc[2][2] = ffma2(a23.x, bd2, acc[2][2]); acc[2][3] = ffma2(a23.x, bd3, acc[2][3]);
            acc[3][0] = ffma2(a23.y, bd0, acc[3][0]); acc[3][1] = ffma2(a23.y, bd1, acc[3][1]);
            acc[3][2] = ffma2(a23.y, bd2, acc[3][2]); acc[3][3] = ffma2(a23.y, bd3, acc[3][3]);
        }
        __syncthreads();
    }

    #pragma unroll
    for (int mp = 0; mp < 4; mp++) {
        int m0 = bm + ty * 8 + mp * 2;
        float2 f0 = unpack2(acc[mp][0]), f1 = unpack2(acc[mp][1]);
        float2 f2 = unpack2(acc[mp][2]), f3 = unpack2(acc[mp][3]);
        float rows[2][4] = {{f0.x, f1.x, f2.x, f3.x}, {f0.y, f1.y, f2.y, f3.y}};
        #pragma unroll
        for (int rr = 0; rr < 2; rr++) {
            uint4 hi, lo;
            cvt_hilo(rows[rr][0], hi.x, lo.x);
            cvt_hilo(rows[rr][1], hi.y, lo.y);
            cvt_hilo(rows[rr][2], hi.z, lo.z);
            cvt_hilo(rows[rr][3], hi.w, lo.w);
            size_t idx = (size_t)(m0 + rr) * 256 + bn + tx * 4;
            *(uint4*)&z_hi_g[idx] = hi;
            *(uint4*)&z_lo_g[idx] = lo;
        }
    }
}

// ---------------------------------------------------------------------------
// dec2: d1 = scatter(G)+BN+relu, then d2, d3. 2 images per block.
// ---------------------------------------------------------------------------
__global__ __launch_bounds__(256) void dec2_kernel(
    const float* __restrict__ bd1,
    const float* __restrict__ gd1, const float* __restrict__ btd1,
    const float* __restrict__ wd2, const float* __restrict__ bd2,
    const float* __restrict__ gd2, const float* __restrict__ btd2,
    const float* __restrict__ wd3, const float* __restrict__ bd3,
    float* __restrict__ out)
{
    extern __shared__ float sm[];
    float* Gs   = sm;                 // 2 * 3600
    float* d1s  = Gs + 7200;          // 2 * 784
    float* d2s  = d1s + 1568;         // 2 * 1568
    float* wd2s = d2s + 3136;         // 1152
    float* wd3s = wd2s + 1152;        // 72

    const int t = threadIdx.x;
    const int b0 = blockIdx.x * 2;
    const float rs = rsqrtf(1.f + BEPS);

    for (int i = t; i < 7200; i += 256) Gs[i] = G_g[(size_t)b0 * 3600 + i];
    for (int i = t; i < 1152; i += 256) wd2s[i] = wd2[i];
    if (t < 72) wd3s[t] = wd3[t];
    __syncthreads();

    for (int idx = t; idx < 1568; idx += 256) {
        int img = idx / 784, r = idx - img * 784;
        int o = r / 49, pos = r - o * 49;
        int oi = pos / 7, oj = pos % 7;
        int y0 = max(oi - 2, 0), y1 = min(oi, 4);
        int x0 = max(oj - 2, 0), x1 = min(oj, 4);
        float sum = 0.f;
        const float* Gb = &Gs[img * 3600];
        for (int y = y0; y <= y1; y++) {
            int ki = oi - y;
            for (int xx = x0; xx <= x1; xx++) {
                int kj = oj - xx;
                sum += Gb[(y * 5 + xx) * 144 + o * 9 + ki * 3 + kj];
            }
        }
        float s = gd1[o] * rs;
        d1s[img * 784 + o * 49 + pos] = fmaxf((sum + bd1[o]) * s + btd1[o], 0.f);
    }
    __syncthreads();

    if (t < 196) {
        float acc2[2][8];
        #pragma unroll
        for (int a = 0; a < 2; a++)
            #pragma unroll
            for (int o = 0; o < 8; o++) acc2[a][o] = 0.f;
        int i = t / 14, j = t % 14;
        int ylo = i / 2, yhi = min((i + 1) / 2, 6);
        int xlo = j / 2, xhi = min((j + 1) / 2, 6);
        for (int c = 0; c < 16; c++) {
            for (int y = ylo; y <= yhi; y++) {
                int ki = i - 2 * y + 1;
                for (int xx = xlo; xx <= xhi; xx++) {
                    int kj = j - 2 * xx + 1;
                    float u0 = d1s[0 * 784 + c * 49 + y * 7 + xx];
                    float u1 = d1s[1 * 784 + c * 49 + y * 7 + xx];
                    #pragma unroll
                    for (int o = 0; o < 8; o++) {
                        float wv = wd2s[((c * 8 + o) * 3 + ki) * 3 + kj];
                        acc2[0][o] += u0 * wv;
                        acc2[1][o] += u1 * wv;
                    }
                }
            }
        }
        #pragma unroll
        for (int o = 0; o < 8; o++) {
            float s = gd2[o] * rs;
            float bias = bd2[o] * s + btd2[o];
            #pragma unroll
            for (int a = 0; a < 2; a++)
                d2s[a * 1568 + o * 196 + t] = fmaxf(acc2[a][o] * s + bias, 0.f);
        }
    }
    __syncthreads();

    const float bb3 = bd3[0];
    for (int idx = t; idx < 1568; idx += 256) {
        int a = idx / 784, p = idx - a * 784, i = p / 28, j = p % 28;
        int ylo = i / 2, yhi = min((i + 1) / 2, 13);
        int xlo = j / 2, xhi = min((j + 1) / 2, 13);
        float acc3 = bb3;
        for (int c = 0; c < 8; c++) {
            for (int y = ylo; y <= yhi; y++) {
                int ki = i - 2 * y + 1;
                for (int xx = xlo; xx <= xhi; xx++) {
                    int kj = j - 2 * xx + 1;
                    acc3 += d2s[a * 1568 + c * 196 + y * 14 + xx] * wd3s[c * 9 + ki * 3 + kj];
                }
            }
        }
        out[(size_t)(b0 + a) * 784 + p] = 1.f / (1.f + expf(-acc3));
    }
}

// ---------------------------------------------------------------------------
extern "C" void kernel_launch(void* const* d_in, const int* in_sizes, int n_in,
                              void* d_out, int out_size)
{
    const float* x     = (const float*)d_in[0];
    const float* w1    = (const float*)d_in[1];
    const float* b1    = (const float*)d_in[2];
    const float* w2    = (const float*)d_in[3];
    const float* b2    = (const float*)d_in[4];
    const float* g2    = (const float*)d_in[5];
    const float* bt2   = (const float*)d_in[6];
    const float* w3    = (const float*)d_in[7];
    const float* b3    = (const float*)d_in[8];
    const float* proto = (const float*)d_in[9];
    const float* wup   = (const float*)d_in[10];
    const float* bup   = (const float*)d_in[11];
    const float* gup   = (const float*)d_in[12];
    const float* btup  = (const float*)d_in[13];
    const float* wd1   = (const float*)d_in[14];
    const float* bd1   = (const float*)d_in[15];
    const float* gd1   = (const float*)d_in[16];
    const float* btd1  = (const float*)d_in[17];
    const float* wd2   = (const float*)d_in[18];
    const float* bd2   = (const float*)d_in[19];
    const float* gd2   = (const float*)d_in[20];
    const float* btd2  = (const float*)d_in[21];
    const float* wd3   = (const float*)d_in[22];
    const float* bd3   = (const float*)d_in[23];

    float* out  = (float*)d_out;                 // (4096,1,28,28)
    float* minD = out + (size_t)NB * 784;        // (4096,512)

    prep_kernel<<<256, 256>>>(proto, w3, wup);
    enc12_kernel<<<NB, 128>>>(x, w1, b1, w2, b2, g2, bt2);
    conv3_kernel<<<NB, 256>>>(b3);
    x2_kernel<<<(NB * 25) / 8, 256>>>();
    init_mind_kernel<<<NB, 512>>>(minD);

    cudaFuncSetAttribute(xp_gemm_kernel, cudaFuncAttributeMaxDynamicSharedMemorySize, PIPE_SMEM);
    dim3 gx(512 / 128, (NB * 25) / 128);         // (4, 800)
    xp_gemm_kernel<<<gx, 256, PIPE_SMEM>>>(minD);

    softmax_kernel<<<NB, 512>>>(minD);

    dim3 gz(256 / 64, NB / 128);
    z_gemm_kernel<<<gz, 256>>>(proto);

    cudaFuncSetAttribute(up_gemm_kernel, cudaFuncAttributeMaxDynamicSharedMemorySize, PIPE_SMEM);
    dim3 gu(6400 / 128, NB / 128);               // (50, 32)
    up_gemm_kernel<<<gu, 256, PIPE_SMEM>>>(bup, gup, btup);

    g_gemm_kernel<<<(NB * 25) / 128, 512>>>(wd1);   // 800 blocks

    size_t smem2 = (size_t)(7200 + 1568 + 3136 + 1152 + 72) * sizeof(float); // 52,512 B
    cudaFuncSetAttribute(dec2_kernel, cudaFuncAttributeMaxDynamicSharedMemorySize, (int)smem2);
    dec2_kernel<<<NB / 2, 256, smem2>>>(bd1, gd1, btd1,
                                        wd2, bd2, gd2, btd2,
                                        wd3, bd3, out);
}

// round 13
// speedup vs baseline: 1.0760x; 1.0701x over previous
#include <cuda_runtime.h>
#include <math.h>
#include <stdint.h>

#define BEPS 1e-5f
#define NB 4096
#define INFBITS 0x7F800000u

// ---------------- scratch (allocation-free) ----------------
__device__ float h2_g[NB * 784];
__device__ float h3T_g[(size_t)NB * 25 * 256];        // [(b*25+pos)][d]
__device__ uint32_t h3T_hi_g[(size_t)NB * 25 * 256];  // tf32 hi
__device__ uint32_t h3T_lo_g[(size_t)NB * 25 * 256];  // tf32 lo
__device__ float x2_g[(size_t)NB * 25];               // per-row squared norm
__device__ float w_g[NB * 512];
__device__ uint32_t z_hi_g[NB * 256];
__device__ float up2_g[(size_t)NB * 6400];            // [(b*25+pos)][c]
__device__ float G_g[(size_t)NB * 25 * 144];          // [(b*25+pos)][o*9+tap]
__device__ float protoT_g[256 * 512];                 // [d][p] raw (z_gemm B)
__device__ uint32_t protoT_hi_g[256 * 512];           // [k][n] tf32 hi
__device__ uint32_t protoT_lo_g[256 * 512];
__device__ uint32_t wupPT_hi_g[256 * 6400];           // [k][pos*256+c]
__device__ uint32_t wupPT_lo_g[256 * 6400];
__device__ float pp_g[512];                           // sum_d proto^2
__device__ float w3t_g[256 * 144];                    // [(c*9+tap)][oc]

// ---------------- packed fp32x2 helpers ----------------
static __device__ __forceinline__ unsigned long long ffma2(
    unsigned long long a, unsigned long long b, unsigned long long c) {
    unsigned long long d;
    asm("fma.rn.f32x2 %0, %1, %2, %3;" : "=l"(d) : "l"(a), "l"(b), "l"(c));
    return d;
}
static __device__ __forceinline__ unsigned long long pack2(float x, float y) {
    unsigned long long r;
    asm("mov.b64 %0, {%1, %2};" : "=l"(r) : "f"(x), "f"(y));
    return r;
}
static __device__ __forceinline__ float2 unpack2(unsigned long long v) {
    float2 r;
    asm("mov.b64 {%0, %1}, %2;" : "=f"(r.x), "=f"(r.y) : "l"(v));
    return r;
}

// ---------------- tf32 helpers ----------------
static __device__ __forceinline__ void cvt_hilo(float x, uint32_t& hi, uint32_t& lo) {
    uint32_t h;
    asm("cvt.rna.tf32.f32 %0, %1;" : "=r"(h) : "f"(x));
    float hf = __uint_as_float(h);
    float l = x - hf;
    asm("cvt.rna.tf32.f32 %0, %1;" : "=r"(lo) : "f"(l));
    hi = h;
}
static __device__ __forceinline__ uint32_t cvt_hi(float x) {
    uint32_t h;
    asm("cvt.rna.tf32.f32 %0, %1;" : "=r"(h) : "f"(x));
    return h;
}
static __device__ __forceinline__ void mma_tf32(float* c, const uint32_t* a, const uint32_t* b) {
    asm volatile(
        "mma.sync.aligned.m16n8k8.row.col.f32.tf32.tf32.f32 "
        "{%0,%1,%2,%3}, {%4,%5,%6,%7}, {%8,%9}, {%0,%1,%2,%3};"
        : "+f"(c[0]), "+f"(c[1]), "+f"(c[2]), "+f"(c[3])
        : "r"(a[0]), "r"(a[1]), "r"(a[2]), "r"(a[3]), "r"(b[0]), "r"(b[1]));
}

// ---------------- cp.async helpers ----------------
static __device__ __forceinline__ uint32_t smem_u32(const void* p) {
    uint32_t a;
    asm("{ .reg .u64 t; cvta.to.shared.u64 t, %1; cvt.u32.u64 %0, t; }" : "=r"(a) : "l"(p));
    return a;
}
#define CPASYNC16(dst, src) \
    asm volatile("cp.async.cg.shared.global [%0], [%1], 16;" :: "r"(dst), "l"(src) : "memory")
#define CPCOMMIT() asm volatile("cp.async.commit_group;" ::: "memory")
#define CPWAIT1() asm volatile("cp.async.wait_group 1;" ::: "memory")
#define CPWAIT0() asm volatile("cp.async.wait_group 0;" ::: "memory")

// ---------------------------------------------------------------------------
// prep: hi/lo splits + transposes + proto norms
// ---------------------------------------------------------------------------
__global__ void prep_kernel(const float* __restrict__ proto,
                            const float* __restrict__ w3,
                            const float* __restrict__ wup)
{
    int stride = gridDim.x * blockDim.x;
    int tid = blockIdx.x * blockDim.x + threadIdx.x;
    for (int i = tid; i < 512 * 256; i += stride) {
        int d = i >> 9, p = i & 511;
        float v = proto[p * 256 + d];
        protoT_g[i] = v;
        uint32_t hi, lo;
        cvt_hilo(v, hi, lo);
        protoT_hi_g[i] = hi;
        protoT_lo_g[i] = lo;
    }
    for (int p = tid; p < 512; p += stride) {
        float s = 0.f;
        for (int d = 0; d < 256; d++) {
            float v = proto[p * 256 + d];
            s += v * v;
        }
        pp_g[p] = s;
    }
    for (int i = tid; i < 256 * 144; i += stride) {
        int o = i & 255, ct = i >> 8;
        int c = ct / 9, tap = ct - c * 9;
        w3t_g[i] = w3[o * 144 + c * 9 + tap];
    }
    for (int i = tid; i < 256 * 6400; i += stride) {
        int k = i / 6400, rr = i % 6400;
        int pos = rr >> 8, c = rr & 255;
        float v = wup[(size_t)k * 6400 + c * 25 + pos];
        uint32_t hi, lo;
        cvt_hilo(v, hi, lo);
        wupPT_hi_g[i] = hi;
        wupPT_lo_g[i] = lo;
    }
}

// ---------------------------------------------------------------------------
// init minD to +inf
// ---------------------------------------------------------------------------
__global__ __launch_bounds__(512) void init_mind_kernel(float* __restrict__ minD)
{
    minD[(size_t)blockIdx.x * 512 + threadIdx.x] = __uint_as_float(INFBITS);
}

// ---------------------------------------------------------------------------
// enc12: conv1 + conv2, one block per image
// ---------------------------------------------------------------------------
__global__ __launch_bounds__(128) void enc12_kernel(
    const float* __restrict__ x,
    const float* __restrict__ w1, const float* __restrict__ b1,
    const float* __restrict__ w2, const float* __restrict__ b2,
    const float* __restrict__ g2, const float* __restrict__ bt2)
{
    __shared__ float xs[784];
    __shared__ float h1s[8 * 196];
    const int b = blockIdx.x;
    const int t = threadIdx.x;

    const float* xb = x + b * 784;
    for (int i = t; i < 784; i += 128) xs[i] = xb[i];
    __syncthreads();

    for (int idx = t; idx < 1568; idx += 128) {
        int o = idx / 196, r = idx % 196, i = r / 14, j = r % 14;
        float acc = b1[o];
        #pragma unroll
        for (int ky = 0; ky < 3; ky++) {
            int y = 2 * i - 1 + ky;
            if ((unsigned)y >= 28u) continue;
            #pragma unroll
            for (int kx = 0; kx < 3; kx++) {
                int xx = 2 * j - 1 + kx;
                if ((unsigned)xx >= 28u) continue;
                acc += xs[y * 28 + xx] * w1[o * 9 + ky * 3 + kx];
            }
        }
        h1s[idx] = fmaxf(acc, 0.f);
    }
    __syncthreads();

    const float rs = rsqrtf(1.f + BEPS);
    for (int idx = t; idx < 784; idx += 128) {
        int o = idx / 49, r = idx % 49, i = r / 7, j = r % 7;
        float acc = 0.f;
        for (int c = 0; c < 8; c++) {
            #pragma unroll
            for (int ky = 0; ky < 3; ky++) {
                int y = 2 * i - 1 + ky;
                if ((unsigned)y >= 14u) continue;
                #pragma unroll
                for (int kx = 0; kx < 3; kx++) {
                    int xx = 2 * j - 1 + kx;
                    if ((unsigned)xx >= 14u) continue;
                    acc += h1s[c * 196 + y * 14 + xx] * w2[((o * 8 + c) * 3 + ky) * 3 + kx];
                }
            }
        }
        float s = g2[o] * rs;
        h2_g[b * 784 + idx] = fmaxf((acc + b2[o]) * s + bt2[o], 0.f);
    }
}

// ---------------------------------------------------------------------------
// conv3: 16->256 k3 s1 p0, 7->5; writes h3T raw + tf32 hi/lo
// ---------------------------------------------------------------------------
__global__ __launch_bounds__(256, 2) void conv3_kernel(const float* __restrict__ b3)
{
    __shared__ float h2s[784];
    const int b = blockIdx.x;
    const int t = threadIdx.x;

    for (int i = t; i < 784; i += 256) h2s[i] = h2_g[b * 784 + i];
    __syncthreads();

    float acc[25];
    #pragma unroll
    for (int p = 0; p < 25; p++) acc[p] = 0.f;

    for (int c = 0; c < 16; c++) {
        float w[9];
        #pragma unroll
        for (int tap = 0; tap < 9; tap++) w[tap] = w3t_g[(c * 9 + tap) * 256 + t];
        float h[49];
        #pragma unroll
        for (int i = 0; i < 49; i++) h[i] = h2s[c * 49 + i];
        #pragma unroll
        for (int ky = 0; ky < 3; ky++)
            #pragma unroll
            for (int kx = 0; kx < 3; kx++) {
                float wv = w[ky * 3 + kx];
                #pragma unroll
                for (int i = 0; i < 5; i++)
                    #pragma unroll
                    for (int j = 0; j < 5; j++)
                        acc[i * 5 + j] += wv * h[(i + ky) * 7 + (j + kx)];
            }
    }
    float bb = b3[t];
    #pragma unroll
    for (int p = 0; p < 25; p++) {
        float v = fmaxf(acc[p] + bb, 0.f);
        size_t idx = ((size_t)b * 25 + p) * 256 + t;
        h3T_g[idx] = v;
        uint32_t hi, lo;
        cvt_hilo(v, hi, lo);
        h3T_hi_g[idx] = hi;
        h3T_lo_g[idx] = lo;
    }
}

// ---------------------------------------------------------------------------
// x2: per-row squared norm of h3T (warp per row)
// ---------------------------------------------------------------------------
__global__ __launch_bounds__(256) void x2_kernel()
{
    const int wid = threadIdx.x >> 5, lane = threadIdx.x & 31;
    const size_t row = (size_t)blockIdx.x * 8 + wid;
    const float* r = &h3T_g[row * 256];
    float s = 0.f;
    #pragma unroll
    for (int j = 0; j < 8; j++) {
        float v = r[lane + 32 * j];
        s += v * v;
    }
    #pragma unroll
    for (int off = 16; off; off >>= 1) s += __shfl_xor_sync(0xffffffffu, s, off);
    if (!lane) x2_g[row] = s;
}

// ===========================================================================
// TF32 GEMM cores with PRE-SPLIT hi/lo operands — no cvt in the mainloop.
// Block 128x128, 8 warps (4m x 2n), warp tile 32x64, k-chunk 16, 2 stages.
// USE_ALO=true  -> 3-pass (hi*hi + hi*lo + lo*hi)   [xp]
// USE_ALO=false -> 2-pass (hi*hi + hi*lo), A lo skipped entirely  [up]
// ===========================================================================
#define ASTR 20
#define BSTR 136
#define ASTG16 (128 * ASTR)
#define BSTG16 (16 * BSTR)
#define OFF_AL (2 * ASTG16)
#define OFF_BH (4 * ASTG16)
#define OFF_BL (4 * ASTG16 + 2 * BSTG16)
#define PIPE_SMEM ((4 * ASTG16 + 4 * BSTG16) * 4)   // 75,776 bytes

template <bool USE_ALO>
static __device__ __forceinline__ void gemm_hilo_core(
    uint32_t* smp,
    const uint32_t* __restrict__ gAh, const uint32_t* __restrict__ gAl, size_t arow0,
    const uint32_t* __restrict__ gBh, const uint32_t* __restrict__ gBl, size_t bcol0,
    int ldb, float acc[2][8][4], int t)
{
    const int lane = t & 31, wid = t >> 5;
    const int wm = wid & 3, wn = wid >> 2;

    const int ar = t >> 1, ak = (t & 1) * 8;
    const int br = t >> 4, bn8 = (t & 15) * 8;
    const uint32_t smb = smem_u32(smp);
    const uint32_t sAh = smb + (uint32_t)(ar * ASTR + ak) * 4;
    const uint32_t sAl = sAh + OFF_AL * 4;
    const uint32_t sBh = smb + (uint32_t)(OFF_BH + br * BSTR + bn8) * 4;
    const uint32_t sBl = sBh + 2 * BSTG16 * 4;
    const uint32_t* gA_h = gAh + (arow0 + ar) * 256 + ak;
    const uint32_t* gA_l = USE_ALO ? (gAl + (arow0 + ar) * 256 + ak) : gA_h;
    const uint32_t* gB_h = gBh + (size_t)br * ldb + bcol0 + bn8;
    const uint32_t* gB_l = gBl + (size_t)br * ldb + bcol0 + bn8;

    CPASYNC16(sAh, gA_h);          CPASYNC16(sAh + 16, gA_h + 4);
    if (USE_ALO) { CPASYNC16(sAl, gA_l); CPASYNC16(sAl + 16, gA_l + 4); }
    CPASYNC16(sBh, gB_h);          CPASYNC16(sBh + 16, gB_h + 4);
    CPASYNC16(sBl, gB_l);          CPASYNC16(sBl + 16, gB_l + 4);
    CPCOMMIT();

    for (int c = 0; c < 16; c++) {
        if (c < 15) {
            const int k0 = (c + 1) * 16;
            const uint32_t st = (uint32_t)((c + 1) & 1);
            uint32_t dAh = sAh + st * ASTG16 * 4;
            uint32_t dAl = sAl + st * ASTG16 * 4;
            uint32_t dBh = sBh + st * BSTG16 * 4;
            uint32_t dBl = sBl + st * BSTG16 * 4;
            CPASYNC16(dAh, gA_h + k0);      CPASYNC16(dAh + 16, gA_h + k0 + 4);
            if (USE_ALO) { CPASYNC16(dAl, gA_l + k0); CPASYNC16(dAl + 16, gA_l + k0 + 4); }
            CPASYNC16(dBh, gB_h + (size_t)k0 * ldb);
            CPASYNC16(dBh + 16, gB_h + (size_t)k0 * ldb + 4);
            CPASYNC16(dBl, gB_l + (size_t)k0 * ldb);
            CPASYNC16(dBl + 16, gB_l + (size_t)k0 * ldb + 4);
            CPCOMMIT();
            CPWAIT1();
        } else {
            CPWAIT0();
        }
        __syncthreads();

        const uint32_t st = (uint32_t)(c & 1);
        const uint32_t* Ah = smp + st * ASTG16;
        const uint32_t* Al = Ah + OFF_AL;
        const uint32_t* Bh = smp + OFF_BH + st * BSTG16;
        const uint32_t* Bl = Bh + 2 * BSTG16;

        #pragma unroll
        for (int ks = 0; ks < 2; ks++) {
            const int col = ks * 8 + (lane & 3);
            uint32_t ah[2][4], al[2][4];
            #pragma unroll
            for (int ms = 0; ms < 2; ms++) {
                int mb = wm * 32 + ms * 16 + (lane >> 2);
                ah[ms][0] = Ah[mb * ASTR + col];
                ah[ms][1] = Ah[(mb + 8) * ASTR + col];
                ah[ms][2] = Ah[mb * ASTR + col + 4];
                ah[ms][3] = Ah[(mb + 8) * ASTR + col + 4];
                if (USE_ALO) {
                    al[ms][0] = Al[mb * ASTR + col];
                    al[ms][1] = Al[(mb + 8) * ASTR + col];
                    al[ms][2] = Al[mb * ASTR + col + 4];
                    al[ms][3] = Al[(mb + 8) * ASTR + col + 4];
                }
            }
            const int row = ks * 8 + (lane & 3);
            #pragma unroll
            for (int nt = 0; nt < 8; nt++) {
                int nb = wn * 64 + nt * 8 + (lane >> 2);
                uint32_t bh[2], bl[2];
                bh[0] = Bh[row * BSTR + nb];
                bh[1] = Bh[(row + 4) * BSTR + nb];
                bl[0] = Bl[row * BSTR + nb];
                bl[1] = Bl[(row + 4) * BSTR + nb];
                #pragma unroll
                for (int ms = 0; ms < 2; ms++) {
                    mma_tf32(acc[ms][nt], ah[ms], bh);
                    mma_tf32(acc[ms][nt], ah[ms], bl);
                    if (USE_ALO) mma_tf32(acc[ms][nt], al[ms], bh);
                }
            }
        }
        __syncthreads();
    }
}

// xp GEMM + fused distance/min: minD[b][p] = min_pos relu(x2 - 2*xp + pp)
__global__ __launch_bounds__(256, 2) void xp_gemm_kernel(float* __restrict__ minD)
{
    extern __shared__ __align__(16) uint32_t smp[];
    const int t = threadIdx.x;
    const int lane = t & 31, wid = t >> 5;
    const int wm = wid & 3, wn = wid >> 2;
    const size_t bm = (size_t)blockIdx.y * 128;
    const int bn = blockIdx.x * 128;

    float acc[2][8][4];
    #pragma unroll
    for (int i = 0; i < 2; i++)
        #pragma unroll
        for (int j = 0; j < 8; j++)
            #pragma unroll
            for (int k = 0; k < 4; k++) acc[i][j][k] = 0.f;

    gemm_hilo_core<true>(smp, h3T_hi_g, h3T_lo_g, bm,
                         protoT_hi_g, protoT_lo_g, bn, 512, acc, t);

    // ---- epilogue: distances + min over pos ----
    unsigned* minred = (unsigned*)smp;           // [8][128]
    float* pps = (float*)(smp + 1024);           // [128]
    for (int i = t; i < 1024; i += 256) minred[i] = INFBITS;
    if (t < 128) pps[t] = pp_g[bn + t];
    __syncthreads();

    const int img0 = (int)(bm / 25);

    float x2v[2][2];
    #pragma unroll
    for (int ms = 0; ms < 2; ms++) {
        int r0 = wm * 32 + ms * 16 + (lane >> 2);
        x2v[ms][0] = x2_g[bm + r0];
        x2v[ms][1] = x2_g[bm + r0 + 8];
    }

    #pragma unroll
    for (int ms = 0; ms < 2; ms++) {
        int r0 = wm * 32 + ms * 16 + (lane >> 2);
        int slot0 = (int)((bm + r0) / 25) - img0;
        int slot1 = (int)((bm + r0 + 8) / 25) - img0;
        #pragma unroll
        for (int nt = 0; nt < 8; nt++) {
            int ncol = wn * 64 + nt * 8 + 2 * (lane & 3);
            float p0 = pps[ncol], p1 = pps[ncol + 1];
            float d00 = fmaxf(x2v[ms][0] - 2.f * acc[ms][nt][0] + p0, 0.f);
            float d01 = fmaxf(x2v[ms][0] - 2.f * acc[ms][nt][1] + p1, 0.f);
            float d10 = fmaxf(x2v[ms][1] - 2.f * acc[ms][nt][2] + p0, 0.f);
            float d11 = fmaxf(x2v[ms][1] - 2.f * acc[ms][nt][3] + p1, 0.f);
            atomicMin(&minred[slot0 * 128 + ncol], __float_as_uint(d00));
            atomicMin(&minred[slot0 * 128 + ncol + 1], __float_as_uint(d01));
            atomicMin(&minred[slot1 * 128 + ncol], __float_as_uint(d10));
            atomicMin(&minred[slot1 * 128 + ncol + 1], __float_as_uint(d11));
        }
    }
    __syncthreads();

    for (int i = t; i < 1024; i += 256) {
        unsigned v = minred[i];
        if (v != INFBITS) {
            int slot = i >> 7, col = i & 127;
            atomicMin((unsigned*)&minD[(size_t)(img0 + slot) * 512 + bn + col], v);
        }
    }
}

// up GEMM (2-pass): C[4096x6400] = z * wupPT, BN+relu, col n = pos*256+c
__global__ __launch_bounds__(256, 2) void up_gemm_kernel(
    const float* __restrict__ bup,
    const float* __restrict__ gup, const float* __restrict__ btup)
{
    extern __shared__ __align__(16) uint32_t smp[];
    const int t = threadIdx.x;
    const int lane = t & 31, wid = t >> 5;
    const int wm = wid & 3, wn = wid >> 2;
    const size_t bm = (size_t)blockIdx.y * 128;
    const int bn = blockIdx.x * 128;

    float acc[2][8][4];
    #pragma unroll
    for (int i = 0; i < 2; i++)
        #pragma unroll
        for (int j = 0; j < 8; j++)
            #pragma unroll
            for (int k = 0; k < 4; k++) acc[i][j][k] = 0.f;

    gemm_hilo_core<false>(smp, z_hi_g, z_hi_g, bm,
                          wupPT_hi_g, wupPT_lo_g, bn, 6400, acc, t);

    const float rsc = rsqrtf(1.f + BEPS);
    #pragma unroll
    for (int ms = 0; ms < 2; ms++)
        #pragma unroll
        for (int nt = 0; nt < 8; nt++) {
            size_t row0 = bm + wm * 32 + ms * 16 + (lane >> 2);
            int col0 = bn + wn * 64 + nt * 8 + 2 * (lane & 3);
            int c0 = col0 & 255, c1 = (col0 + 1) & 255;
            float s0 = gup[c0] * rsc, s1 = gup[c1] * rsc;
            float bi0 = bup[c0] * s0 + btup[c0];
            float bi1 = bup[c1] * s1 + btup[c1];
            *(float2*)&up2_g[row0 * 6400 + col0] =
                make_float2(fmaxf(acc[ms][nt][0] * s0 + bi0, 0.f),
                            fmaxf(acc[ms][nt][1] * s1 + bi1, 0.f));
            *(float2*)&up2_g[(row0 + 8) * 6400 + col0] =
                make_float2(fmaxf(acc[ms][nt][2] * s0 + bi0, 0.f),
                            fmaxf(acc[ms][nt][3] * s1 + bi1, 0.f));
        }
}

// ---------------------------------------------------------------------------
// g GEMM (2-pass, in-loop cvt; A hi only): G[102400x144] = up2 * wd1
// ---------------------------------------------------------------------------
#define AS_STRIDE 36
#define GBS_STRIDE 152
__global__ __launch_bounds__(512, 1) void g_gemm_kernel(const float* __restrict__ wd1)
{
    __shared__ float As[128 * AS_STRIDE];
    __shared__ float Bs[32 * GBS_STRIDE];

    const int t = threadIdx.x;
    const int lane = t & 31, wid = t >> 5;
    const int wm = wid & 7, wn = wid >> 3;
    const int bm = blockIdx.x * 128;

    float acc[9][4];
    #pragma unroll
    for (int j = 0; j < 9; j++)
        #pragma unroll
        for (int k = 0; k < 4; k++) acc[j][k] = 0.f;

    const int ar = t >> 2, ak = (t & 3) * 8;

    for (int k0 = 0; k0 < 256; k0 += 32) {
        const float* asrc = &up2_g[(size_t)(bm + ar) * 256 + k0 + ak];
        float4 av0 = *(const float4*)asrc;
        float4 av1 = *(const float4*)(asrc + 4);
        float bvals[9];
        #pragma unroll
        for (int j = 0; j < 9; j++) {
            int i = t + j * 512;
            int row = i / 144, col = i - row * 144;
            bvals[j] = wd1[(size_t)(k0 + row) * 144 + col];
        }
        __syncthreads();
        *(float4*)&As[ar * AS_STRIDE + ak]     = av0;
        *(float4*)&As[ar * AS_STRIDE + ak + 4] = av1;
        #pragma unroll
        for (int j = 0; j < 9; j++) {
            int i = t + j * 512;
            int row = i / 144, col = i - row * 144;
            Bs[row * GBS_STRIDE + col] = bvals[j];
        }
        __syncthreads();

        #pragma unroll
        for (int ks = 0; ks < 4; ks++) {
            const int col = ks * 8 + (lane & 3);
            uint32_t ah[4];
            {
                int mb = wm * 16 + (lane >> 2);
                ah[0] = cvt_hi(As[mb * AS_STRIDE + col]);
                ah[1] = cvt_hi(As[(mb + 8) * AS_STRIDE + col]);
                ah[2] = cvt_hi(As[mb * AS_STRIDE + col + 4]);
                ah[3] = cvt_hi(As[(mb + 8) * AS_STRIDE + col + 4]);
            }
            const int row = ks * 8 + (lane & 3);
            #pragma unroll
            for (int nt = 0; nt < 9; nt++) {
                int nb = wn * 72 + nt * 8 + (lane >> 2);
                float y0 = Bs[row * GBS_STRIDE + nb];
                float y1 = Bs[(row + 4) * GBS_STRIDE + nb];
                uint32_t bh[2], bl[2];
                cvt_hilo(y0, bh[0], bl[0]);
                cvt_hilo(y1, bh[1], bl[1]);
                mma_tf32(acc[nt], ah, bh);
                mma_tf32(acc[nt], ah, bl);
            }
        }
    }

    #pragma unroll
    for (int nt = 0; nt < 9; nt++) {
        int row0 = bm + wm * 16 + (lane >> 2);
        int col0 = wn * 72 + nt * 8 + 2 * (lane & 3);
        *(float2*)&G_g[(size_t)row0 * 144 + col0] = make_float2(acc[nt][0], acc[nt][1]);
        *(float2*)&G_g[(size_t)(row0 + 8) * 144 + col0] = make_float2(acc[nt][2], acc[nt][3]);
    }
}

// ---------------------------------------------------------------------------
// softmax over minD -> w_g
// ---------------------------------------------------------------------------
__global__ __launch_bounds__(512) void softmax_kernel(const float* __restrict__ minD)
{
    __shared__ float red[32];
    const int b = blockIdx.x;
    const int t = threadIdx.x;
    const int lane = t & 31, wid = t >> 5;

    float m = minD[(size_t)b * 512 + t];
    float a = -m;
    float v = a;
    #pragma unroll
    for (int off = 16; off; off >>= 1) v = fmaxf(v, __shfl_xor_sync(0xffffffffu, v, off));
    if (!lane) red[wid] = v;
    __syncthreads();
    if (t == 0) {
        float r = red[0];
        for (int i = 1; i < 16; i++) r = fmaxf(r, red[i]);
        red[16] = r;
    }
    __syncthreads();
    float amax = red[16];
    float e = expf(a - amax);
    float sv = e;
    #pragma unroll
    for (int off = 16; off; off >>= 1) sv += __shfl_xor_sync(0xffffffffu, sv, off);
    __syncthreads();
    if (!lane) red[wid] = sv;
    __syncthreads();
    if (t == 0) {
        float r = 0.f;
        for (int i = 0; i < 16; i++) r += red[i];
        red[16] = r;
    }
    __syncthreads();
    w_g[(size_t)b * 512 + t] = e * (1.f / red[16]);
}

// ---------------------------------------------------------------------------
// z GEMM (FFMA f32x2): z = w * proto; epilogue emits z hi only
// ---------------------------------------------------------------------------
__global__ __launch_bounds__(256) void z_gemm_kernel(const float* __restrict__ proto)
{
    __shared__ __align__(16) float As2[16][128];
    __shared__ __align__(16) float Bs2[16][64];
    const int bn = blockIdx.x * 64;
    const int bm = blockIdx.y * 128;
    const int t = threadIdx.x;
    const int tx = t & 15, ty = t >> 4;

    unsigned long long acc[4][4];
    #pragma unroll
    for (int i = 0; i < 4; i++)
        #pragma unroll
        for (int j = 0; j < 4; j++) acc[i][j] = 0ull;

    for (int k0 = 0; k0 < 512; k0 += 16) {
        #pragma unroll
        for (int s = t; s < 512; s += 256) {
            int r = s >> 2, kq = (s & 3) << 2;
            float4 v = *(const float4*)&w_g[(size_t)(bm + r) * 512 + k0 + kq];
            As2[kq + 0][r] = v.x; As2[kq + 1][r] = v.y;
            As2[kq + 2][r] = v.z; As2[kq + 3][r] = v.w;
        }
        {
            int kk = t >> 4, n4 = (t & 15) << 2;
            *(float4*)&Bs2[kk][n4] = *(const float4*)&proto[(size_t)(k0 + kk) * 256 + bn + n4];
        }
        __syncthreads();
        #pragma unroll
        for (int kk = 0; kk < 16; kk++) {
            ulonglong2 a01 = *(const ulonglong2*)&As2[kk][ty * 8];
            ulonglong2 a23 = *(const ulonglong2*)&As2[kk][ty * 8 + 4];
            float4 bv = *(const float4*)&Bs2[kk][tx * 4];
            unsigned long long bd0 = pack2(bv.x, bv.x), bd1 = pack2(bv.y, bv.y);
            unsigned long long bd2 = pack2(bv.z, bv.z), bd3 = pack2(bv.w, bv.w);
            acc[0][0] = ffma2(a01.x, bd0, acc[0][0]); acc[0][1] = ffma2(a01.x, bd1, acc[0][1]);
            acc[0][2] = ffma2(a01.x, bd2, acc[0][2]); acc[0][3] = ffma2(a01.x, bd3, acc[0][3]);
            acc[1][0] = ffma2(a01.y, bd0, acc[1][0]); acc[1][1] = ffma2(a01.y, bd1, acc[1][1]);
            acc[1][2] = ffma2(a01.y, bd2, acc[1][2]); acc[1][3] = ffma2(a01.y, bd3, acc[1][3]);
            acc[2][0] = ffma2(a23.x, bd0, acc[2][0]); acc[2][1] = ffma2(a23.x, bd1, acc[2][1]);
            acc[2][2] = ffma2(a23.x, bd2, acc[2][2]); acc[2][3] = ffma2(a23.x, bd3, acc[2][3]);
            acc[3][0] = ffma2(a23.y, bd0, acc[3][0]); acc[3][1] = ffma2(a23.y, bd1, acc[3][1]);
            acc[3][2] = ffma2(a23.y, bd2, acc[3][2]); acc[3][3] = ffma2(a23.y, bd3, acc[3][3]);
        }
        __syncthreads();
    }

    #pragma unroll
    for (int mp = 0; mp < 4; mp++) {
        int m0 = bm + ty * 8 + mp * 2;
        float2 f0 = unpack2(acc[mp][0]), f1 = unpack2(acc[mp][1]);
        float2 f2 = unpack2(acc[mp][2]), f3 = unpack2(acc[mp][3]);
        float rows[2][4] = {{f0.x, f1.x, f2.x, f3.x}, {f0.y, f1.y, f2.y, f3.y}};
        #pragma unroll
        for (int rr = 0; rr < 2; rr++) {
            uint4 hi;
            hi.x = cvt_hi(rows[rr][0]);
            hi.y = cvt_hi(rows[rr][1]);
            hi.z = cvt_hi(rows[rr][2]);
            hi.w = cvt_hi(rows[rr][3]);
            size_t idx = (size_t)(m0 + rr) * 256 + bn + tx * 4;
            *(uint4*)&z_hi_g[idx] = hi;
        }
    }
}

// ---------------------------------------------------------------------------
// dec2: d1 = scatter(G)+BN+relu, then d2, d3. 2 images per block.
// ---------------------------------------------------------------------------
__global__ __launch_bounds__(256) void dec2_kernel(
    const float* __restrict__ bd1,
    const float* __restrict__ gd1, const float* __restrict__ btd1,
    const float* __restrict__ wd2, const float* __restrict__ bd2,
    const float* __restrict__ gd2, const float* __restrict__ btd2,
    const float* __restrict__ wd3, const float* __restrict__ bd3,
    float* __restrict__ out)
{
    extern __shared__ float sm[];
    float* Gs   = sm;                 // 2 * 3600
    float* d1s  = Gs + 7200;          // 2 * 784
    float* d2s  = d1s + 1568;         // 2 * 1568
    float* wd2s = d2s + 3136;         // 1152
    float* wd3s = wd2s + 1152;        // 72

    const int t = threadIdx.x;
    const int b0 = blockIdx.x * 2;
    const float rs = rsqrtf(1.f + BEPS);

    for (int i = t; i < 7200; i += 256) Gs[i] = G_g[(size_t)b0 * 3600 + i];
    for (int i = t; i < 1152; i += 256) wd2s[i] = wd2[i];
    if (t < 72) wd3s[t] = wd3[t];
    __syncthreads();

    for (int idx = t; idx < 1568; idx += 256) {
        int img = idx / 784, r = idx - img * 784;
        int o = r / 49, pos = r - o * 49;
        int oi = pos / 7, oj = pos % 7;
        int y0 = max(oi - 2, 0), y1 = min(oi, 4);
        int x0 = max(oj - 2, 0), x1 = min(oj, 4);
        float sum = 0.f;
        const float* Gb = &Gs[img * 3600];
        for (int y = y0; y <= y1; y++) {
            int ki = oi - y;
            for (int xx = x0; xx <= x1; xx++) {
                int kj = oj - xx;
                sum += Gb[(y * 5 + xx) * 144 + o * 9 + ki * 3 + kj];
            }
        }
        float s = gd1[o] * rs;
        d1s[img * 784 + o * 49 + pos] = fmaxf((sum + bd1[o]) * s + btd1[o], 0.f);
    }
    __syncthreads();

    if (t < 196) {
        float acc2[2][8];
        #pragma unroll
        for (int a = 0; a < 2; a++)
            #pragma unroll
            for (int o = 0; o < 8; o++) acc2[a][o] = 0.f;
        int i = t / 14, j = t % 14;
        int ylo = i / 2, yhi = min((i + 1) / 2, 6);
        int xlo = j / 2, xhi = min((j + 1) / 2, 6);
        for (int c = 0; c < 16; c++) {
            for (int y = ylo; y <= yhi; y++) {
                int ki = i - 2 * y + 1;
                for (int xx = xlo; xx <= xhi; xx++) {
                    int kj = j - 2 * xx + 1;
                    float u0 = d1s[0 * 784 + c * 49 + y * 7 + xx];
                    float u1 = d1s[1 * 784 + c * 49 + y * 7 + xx];
                    #pragma unroll
                    for (int o = 0; o < 8; o++) {
                        float wv = wd2s[((c * 8 + o) * 3 + ki) * 3 + kj];
                        acc2[0][o] += u0 * wv;
                        acc2[1][o] += u1 * wv;
                    }
                }
            }
        }
        #pragma unroll
        for (int o = 0; o < 8; o++) {
            float s = gd2[o] * rs;
            float bias = bd2[o] * s + btd2[o];
            #pragma unroll
            for (int a = 0; a < 2; a++)
                d2s[a * 1568 + o * 196 + t] = fmaxf(acc2[a][o] * s + bias, 0.f);
        }
    }
    __syncthreads();

    const float bb3 = bd3[0];
    for (int idx = t; idx < 1568; idx += 256) {
        int a = idx / 784, p = idx - a * 784, i = p / 28, j = p % 28;
        int ylo = i / 2, yhi = min((i + 1) / 2, 13);
        int xlo = j / 2, xhi = min((j + 1) / 2, 13);
        float acc3 = bb3;
        for (int c = 0; c < 8; c++) {
            for (int y = ylo; y <= yhi; y++) {
                int ki = i - 2 * y + 1;
                for (int xx = xlo; xx <= xhi; xx++) {
                    int kj = j - 2 * xx + 1;
                    acc3 += d2s[a * 1568 + c * 196 + y * 14 + xx] * wd3s[c * 9 + ki * 3 + kj];
                }
            }
        }
        out[(size_t)(b0 + a) * 784 + p] = 1.f / (1.f + expf(-acc3));
    }
}

// ---------------------------------------------------------------------------
extern "C" void kernel_launch(void* const* d_in, const int* in_sizes, int n_in,
                              void* d_out, int out_size)
{
    const float* x     = (const float*)d_in[0];
    const float* w1    = (const float*)d_in[1];
    const float* b1    = (const float*)d_in[2];
    const float* w2    = (const float*)d_in[3];
    const float* b2    = (const float*)d_in[4];
    const float* g2    = (const float*)d_in[5];
    const float* bt2   = (const float*)d_in[6];
    const float* w3    = (const float*)d_in[7];
    const float* b3    = (const float*)d_in[8];
    const float* proto = (const float*)d_in[9];
    const float* wup   = (const float*)d_in[10];
    const float* bup   = (const float*)d_in[11];
    const float* gup   = (const float*)d_in[12];
    const float* btup  = (const float*)d_in[13];
    const float* wd1   = (const float*)d_in[14];
    const float* bd1   = (const float*)d_in[15];
    const float* gd1   = (const float*)d_in[16];
    const float* btd1  = (const float*)d_in[17];
    const float* wd2   = (const float*)d_in[18];
    const float* bd2   = (const float*)d_in[19];
    const float* gd2   = (const float*)d_in[20];
    const float* btd2  = (const float*)d_in[21];
    const float* wd3   = (const float*)d_in[22];
    const float* bd3   = (const float*)d_in[23];

    float* out  = (float*)d_out;                 // (4096,1,28,28)
    float* minD = out + (size_t)NB * 784;        // (4096,512)

    prep_kernel<<<256, 256>>>(proto, w3, wup);
    enc12_kernel<<<NB, 128>>>(x, w1, b1, w2, b2, g2, bt2);
    conv3_kernel<<<NB, 256>>>(b3);
    x2_kernel<<<(NB * 25) / 8, 256>>>();
    init_mind_kernel<<<NB, 512>>>(minD);

    cudaFuncSetAttribute(xp_gemm_kernel, cudaFuncAttributeMaxDynamicSharedMemorySize, PIPE_SMEM);
    dim3 gx(512 / 128, (NB * 25) / 128);         // (4, 800)
    xp_gemm_kernel<<<gx, 256, PIPE_SMEM>>>(minD);

    softmax_kernel<<<NB, 512>>>(minD);

    dim3 gz(256 / 64, NB / 128);
    z_gemm_kernel<<<gz, 256>>>(proto);

    cudaFuncSetAttribute(up_gemm_kernel, cudaFuncAttributeMaxDynamicSharedMemorySize, PIPE_SMEM);
    dim3 gu(6400 / 128, NB / 128);               // (50, 32)
    up_gemm_kernel<<<gu, 256, PIPE_SMEM>>>(bup, gup, btup);

    g_gemm_kernel<<<(NB * 25) / 128, 512>>>(wd1);   // 800 blocks

    size_t smem2 = (size_t)(7200 + 1568 + 3136 + 1152 + 72) * sizeof(float); // 52,512 B
    cudaFuncSetAttribute(dec2_kernel, cudaFuncAttributeMaxDynamicSharedMemorySize, (int)smem2);
    dec2_kernel<<<NB / 2, 256, smem2>>>(bd1, gd1, btd1,
                                        wd2, bd2, gd2, btd2,
                                        wd3, bd3, out);
}

// round 14
// speedup vs baseline: 1.2164x; 1.1305x over previous
#include <cuda_runtime.h>
#include <math.h>
#include <stdint.h>

#define BEPS 1e-5f
#define NB 4096
#define INFBITS 0x7F800000u

// ---------------- scratch (allocation-free) ----------------
__device__ float h2_g[NB * 784];
__device__ float h3T_g[(size_t)NB * 25 * 256];        // [(b*25+pos)][d]
__device__ uint32_t h3T_hi_g[(size_t)NB * 25 * 256];  // tf32 hi
__device__ float x2_g[(size_t)NB * 25];               // per-row squared norm
__device__ float w_g[NB * 512];
__device__ uint32_t z_hi_g[NB * 256];
__device__ float up2_g[(size_t)NB * 6400];            // [(b*25+pos)][c]
__device__ float G_g[(size_t)NB * 25 * 144];          // [(b*25+pos)][o*9+tap]
__device__ float protoT_g[256 * 512];                 // [d][p] raw (z_gemm B)
__device__ uint32_t protoT_hi_g[256 * 512];           // [k][n] tf32 hi
__device__ uint32_t protoT_lo_g[256 * 512];
__device__ uint32_t wupPT_hi_g[256 * 6400];           // [k][pos*256+c]
__device__ uint32_t wupPT_lo_g[256 * 6400];
__device__ float pp_g[512];                           // sum_d proto^2
__device__ float w3t_g[256 * 144];                    // [(c*9+tap)][oc]

// ---------------- packed fp32x2 helpers ----------------
static __device__ __forceinline__ unsigned long long ffma2(
    unsigned long long a, unsigned long long b, unsigned long long c) {
    unsigned long long d;
    asm("fma.rn.f32x2 %0, %1, %2, %3;" : "=l"(d) : "l"(a), "l"(b), "l"(c));
    return d;
}
static __device__ __forceinline__ unsigned long long pack2(float x, float y) {
    unsigned long long r;
    asm("mov.b64 %0, {%1, %2};" : "=l"(r) : "f"(x), "f"(y));
    return r;
}
static __device__ __forceinline__ float2 unpack2(unsigned long long v) {
    float2 r;
    asm("mov.b64 {%0, %1}, %2;" : "=f"(r.x), "=f"(r.y) : "l"(v));
    return r;
}

// ---------------- tf32 helpers ----------------
static __device__ __forceinline__ void cvt_hilo(float x, uint32_t& hi, uint32_t& lo) {
    uint32_t h;
    asm("cvt.rna.tf32.f32 %0, %1;" : "=r"(h) : "f"(x));
    float hf = __uint_as_float(h);
    float l = x - hf;
    asm("cvt.rna.tf32.f32 %0, %1;" : "=r"(lo) : "f"(l));
    hi = h;
}
static __device__ __forceinline__ uint32_t cvt_hi(float x) {
    uint32_t h;
    asm("cvt.rna.tf32.f32 %0, %1;" : "=r"(h) : "f"(x));
    return h;
}
static __device__ __forceinline__ void mma_tf32(float* c, const uint32_t* a, const uint32_t* b) {
    asm volatile(
        "mma.sync.aligned.m16n8k8.row.col.f32.tf32.tf32.f32 "
        "{%0,%1,%2,%3}, {%4,%5,%6,%7}, {%8,%9}, {%0,%1,%2,%3};"
        : "+f"(c[0]), "+f"(c[1]), "+f"(c[2]), "+f"(c[3])
        : "r"(a[0]), "r"(a[1]), "r"(a[2]), "r"(a[3]), "r"(b[0]), "r"(b[1]));
}

// ---------------- cp.async helpers ----------------
static __device__ __forceinline__ uint32_t smem_u32(const void* p) {
    uint32_t a;
    asm("{ .reg .u64 t; cvta.to.shared.u64 t, %1; cvt.u32.u64 %0, t; }" : "=r"(a) : "l"(p));
    return a;
}
#define CPASYNC16(dst, src) \
    asm volatile("cp.async.cg.shared.global [%0], [%1], 16;" :: "r"(dst), "l"(src) : "memory")
#define CPCOMMIT() asm volatile("cp.async.commit_group;" ::: "memory")
#define CPWAIT1() asm volatile("cp.async.wait_group 1;" ::: "memory")
#define CPWAIT0() asm volatile("cp.async.wait_group 0;" ::: "memory")

// ---------------------------------------------------------------------------
// prep: hi/lo splits + transposes + proto norms
// ---------------------------------------------------------------------------
__global__ void prep_kernel(const float* __restrict__ proto,
                            const float* __restrict__ w3,
                            const float* __restrict__ wup)
{
    int stride = gridDim.x * blockDim.x;
    int tid = blockIdx.x * blockDim.x + threadIdx.x;
    for (int i = tid; i < 512 * 256; i += stride) {
        int d = i >> 9, p = i & 511;
        float v = proto[p * 256 + d];
        protoT_g[i] = v;
        uint32_t hi, lo;
        cvt_hilo(v, hi, lo);
        protoT_hi_g[i] = hi;
        protoT_lo_g[i] = lo;
    }
    for (int p = tid; p < 512; p += stride) {
        float s = 0.f;
        for (int d = 0; d < 256; d++) {
            float v = proto[p * 256 + d];
            s += v * v;
        }
        pp_g[p] = s;
    }
    for (int i = tid; i < 256 * 144; i += stride) {
        int o = i & 255, ct = i >> 8;
        int c = ct / 9, tap = ct - c * 9;
        w3t_g[i] = w3[o * 144 + c * 9 + tap];
    }
    for (int i = tid; i < 256 * 6400; i += stride) {
        int k = i / 6400, rr = i % 6400;
        int pos = rr >> 8, c = rr & 255;
        float v = wup[(size_t)k * 6400 + c * 25 + pos];
        uint32_t hi, lo;
        cvt_hilo(v, hi, lo);
        wupPT_hi_g[i] = hi;
        wupPT_lo_g[i] = lo;
    }
}

// ---------------------------------------------------------------------------
// init minD to +inf
// ---------------------------------------------------------------------------
__global__ __launch_bounds__(512) void init_mind_kernel(float* __restrict__ minD)
{
    minD[(size_t)blockIdx.x * 512 + threadIdx.x] = __uint_as_float(INFBITS);
}

// ---------------------------------------------------------------------------
// enc12: conv1 + conv2, one block per image
// ---------------------------------------------------------------------------
__global__ __launch_bounds__(128) void enc12_kernel(
    const float* __restrict__ x,
    const float* __restrict__ w1, const float* __restrict__ b1,
    const float* __restrict__ w2, const float* __restrict__ b2,
    const float* __restrict__ g2, const float* __restrict__ bt2)
{
    __shared__ float xs[784];
    __shared__ float h1s[8 * 196];
    const int b = blockIdx.x;
    const int t = threadIdx.x;

    const float* xb = x + b * 784;
    for (int i = t; i < 784; i += 128) xs[i] = xb[i];
    __syncthreads();

    for (int idx = t; idx < 1568; idx += 128) {
        int o = idx / 196, r = idx % 196, i = r / 14, j = r % 14;
        float acc = b1[o];
        #pragma unroll
        for (int ky = 0; ky < 3; ky++) {
            int y = 2 * i - 1 + ky;
            if ((unsigned)y >= 28u) continue;
            #pragma unroll
            for (int kx = 0; kx < 3; kx++) {
                int xx = 2 * j - 1 + kx;
                if ((unsigned)xx >= 28u) continue;
                acc += xs[y * 28 + xx] * w1[o * 9 + ky * 3 + kx];
            }
        }
        h1s[idx] = fmaxf(acc, 0.f);
    }
    __syncthreads();

    const float rs = rsqrtf(1.f + BEPS);
    for (int idx = t; idx < 784; idx += 128) {
        int o = idx / 49, r = idx % 49, i = r / 7, j = r % 7;
        float acc = 0.f;
        for (int c = 0; c < 8; c++) {
            #pragma unroll
            for (int ky = 0; ky < 3; ky++) {
                int y = 2 * i - 1 + ky;
                if ((unsigned)y >= 14u) continue;
                #pragma unroll
                for (int kx = 0; kx < 3; kx++) {
                    int xx = 2 * j - 1 + kx;
                    if ((unsigned)xx >= 14u) continue;
                    acc += h1s[c * 196 + y * 14 + xx] * w2[((o * 8 + c) * 3 + ky) * 3 + kx];
                }
            }
        }
        float s = g2[o] * rs;
        h2_g[b * 784 + idx] = fmaxf((acc + b2[o]) * s + bt2[o], 0.f);
    }
}

// ---------------------------------------------------------------------------
// conv3: 16->256 k3 s1 p0, 7->5; writes h3T raw + tf32 hi
// ---------------------------------------------------------------------------
__global__ __launch_bounds__(256, 2) void conv3_kernel(const float* __restrict__ b3)
{
    __shared__ float h2s[784];
    const int b = blockIdx.x;
    const int t = threadIdx.x;

    for (int i = t; i < 784; i += 256) h2s[i] = h2_g[b * 784 + i];
    __syncthreads();

    float acc[25];
    #pragma unroll
    for (int p = 0; p < 25; p++) acc[p] = 0.f;

    for (int c = 0; c < 16; c++) {
        float w[9];
        #pragma unroll
        for (int tap = 0; tap < 9; tap++) w[tap] = w3t_g[(c * 9 + tap) * 256 + t];
        float h[49];
        #pragma unroll
        for (int i = 0; i < 49; i++) h[i] = h2s[c * 49 + i];
        #pragma unroll
        for (int ky = 0; ky < 3; ky++)
            #pragma unroll
            for (int kx = 0; kx < 3; kx++) {
                float wv = w[ky * 3 + kx];
                #pragma unroll
                for (int i = 0; i < 5; i++)
                    #pragma unroll
                    for (int j = 0; j < 5; j++)
                        acc[i * 5 + j] += wv * h[(i + ky) * 7 + (j + kx)];
            }
    }
    float bb = b3[t];
    #pragma unroll
    for (int p = 0; p < 25; p++) {
        float v = fmaxf(acc[p] + bb, 0.f);
        size_t idx = ((size_t)b * 25 + p) * 256 + t;
        h3T_g[idx] = v;
        h3T_hi_g[idx] = cvt_hi(v);
    }
}

// ---------------------------------------------------------------------------
// x2: per-row squared norm of h3T (warp per row)
// ---------------------------------------------------------------------------
__global__ __launch_bounds__(256) void x2_kernel()
{
    const int wid = threadIdx.x >> 5, lane = threadIdx.x & 31;
    const size_t row = (size_t)blockIdx.x * 8 + wid;
    const float* r = &h3T_g[row * 256];
    float s = 0.f;
    #pragma unroll
    for (int j = 0; j < 8; j++) {
        float v = r[lane + 32 * j];
        s += v * v;
    }
    #pragma unroll
    for (int off = 16; off; off >>= 1) s += __shfl_xor_sync(0xffffffffu, s, off);
    if (!lane) x2_g[row] = s;
}

// ===========================================================================
// TF32 GEMM cores with PRE-SPLIT hi/lo operands — no cvt in the mainloop.
// Block 128x128, 8 warps (4m x 2n), warp tile 32x64, k-chunk 16, 2 stages.
// USE_ALO=true  -> 3-pass (hi*hi + hi*lo + lo*hi)
// USE_ALO=false -> 2-pass (hi*hi + hi*lo), A lo skipped entirely  [xp, up]
// ===========================================================================
#define ASTR 20
#define BSTR 136
#define ASTG16 (128 * ASTR)
#define BSTG16 (16 * BSTR)
#define OFF_AL (2 * ASTG16)
#define OFF_BH (4 * ASTG16)
#define OFF_BL (4 * ASTG16 + 2 * BSTG16)
#define PIPE_SMEM ((4 * ASTG16 + 4 * BSTG16) * 4)   // 75,776 bytes

template <bool USE_ALO>
static __device__ __forceinline__ void gemm_hilo_core(
    uint32_t* smp,
    const uint32_t* __restrict__ gAh, const uint32_t* __restrict__ gAl, size_t arow0,
    const uint32_t* __restrict__ gBh, const uint32_t* __restrict__ gBl, size_t bcol0,
    int ldb, float acc[2][8][4], int t)
{
    const int lane = t & 31, wid = t >> 5;
    const int wm = wid & 3, wn = wid >> 2;

    const int ar = t >> 1, ak = (t & 1) * 8;
    const int br = t >> 4, bn8 = (t & 15) * 8;
    const uint32_t smb = smem_u32(smp);
    const uint32_t sAh = smb + (uint32_t)(ar * ASTR + ak) * 4;
    const uint32_t sAl = sAh + OFF_AL * 4;
    const uint32_t sBh = smb + (uint32_t)(OFF_BH + br * BSTR + bn8) * 4;
    const uint32_t sBl = sBh + 2 * BSTG16 * 4;
    const uint32_t* gA_h = gAh + (arow0 + ar) * 256 + ak;
    const uint32_t* gA_l = USE_ALO ? (gAl + (arow0 + ar) * 256 + ak) : gA_h;
    const uint32_t* gB_h = gBh + (size_t)br * ldb + bcol0 + bn8;
    const uint32_t* gB_l = gBl + (size_t)br * ldb + bcol0 + bn8;

    CPASYNC16(sAh, gA_h);          CPASYNC16(sAh + 16, gA_h + 4);
    if (USE_ALO) { CPASYNC16(sAl, gA_l); CPASYNC16(sAl + 16, gA_l + 4); }
    CPASYNC16(sBh, gB_h);          CPASYNC16(sBh + 16, gB_h + 4);
    CPASYNC16(sBl, gB_l);          CPASYNC16(sBl + 16, gB_l + 4);
    CPCOMMIT();

    for (int c = 0; c < 16; c++) {
        if (c < 15) {
            const int k0 = (c + 1) * 16;
            const uint32_t st = (uint32_t)((c + 1) & 1);
            uint32_t dAh = sAh + st * ASTG16 * 4;
            uint32_t dAl = sAl + st * ASTG16 * 4;
            uint32_t dBh = sBh + st * BSTG16 * 4;
            uint32_t dBl = sBl + st * BSTG16 * 4;
            CPASYNC16(dAh, gA_h + k0);      CPASYNC16(dAh + 16, gA_h + k0 + 4);
            if (USE_ALO) { CPASYNC16(dAl, gA_l + k0); CPASYNC16(dAl + 16, gA_l + k0 + 4); }
            CPASYNC16(dBh, gB_h + (size_t)k0 * ldb);
            CPASYNC16(dBh + 16, gB_h + (size_t)k0 * ldb + 4);
            CPASYNC16(dBl, gB_l + (size_t)k0 * ldb);
            CPASYNC16(dBl + 16, gB_l + (size_t)k0 * ldb + 4);
            CPCOMMIT();
            CPWAIT1();
        } else {
            CPWAIT0();
        }
        __syncthreads();

        const uint32_t st = (uint32_t)(c & 1);
        const uint32_t* Ah = smp + st * ASTG16;
        const uint32_t* Al = Ah + OFF_AL;
        const uint32_t* Bh = smp + OFF_BH + st * BSTG16;
        const uint32_t* Bl = Bh + 2 * BSTG16;

        #pragma unroll
        for (int ks = 0; ks < 2; ks++) {
            const int col = ks * 8 + (lane & 3);
            uint32_t ah[2][4], al[2][4];
            #pragma unroll
            for (int ms = 0; ms < 2; ms++) {
                int mb = wm * 32 + ms * 16 + (lane >> 2);
                ah[ms][0] = Ah[mb * ASTR + col];
                ah[ms][1] = Ah[(mb + 8) * ASTR + col];
                ah[ms][2] = Ah[mb * ASTR + col + 4];
                ah[ms][3] = Ah[(mb + 8) * ASTR + col + 4];
                if (USE_ALO) {
                    al[ms][0] = Al[mb * ASTR + col];
                    al[ms][1] = Al[(mb + 8) * ASTR + col];
                    al[ms][2] = Al[mb * ASTR + col + 4];
                    al[ms][3] = Al[(mb + 8) * ASTR + col + 4];
                }
            }
            const int row = ks * 8 + (lane & 3);
            #pragma unroll
            for (int nt = 0; nt < 8; nt++) {
                int nb = wn * 64 + nt * 8 + (lane >> 2);
                uint32_t bh[2], bl[2];
                bh[0] = Bh[row * BSTR + nb];
                bh[1] = Bh[(row + 4) * BSTR + nb];
                bl[0] = Bl[row * BSTR + nb];
                bl[1] = Bl[(row + 4) * BSTR + nb];
                #pragma unroll
                for (int ms = 0; ms < 2; ms++) {
                    mma_tf32(acc[ms][nt], ah[ms], bh);
                    mma_tf32(acc[ms][nt], ah[ms], bl);
                    if (USE_ALO) mma_tf32(acc[ms][nt], al[ms], bh);
                }
            }
        }
        __syncthreads();
    }
}

// xp GEMM (2-pass) + fused distance/min: minD[b][p] = min_pos relu(x2 - 2*xp + pp)
__global__ __launch_bounds__(256, 2) void xp_gemm_kernel(float* __restrict__ minD)
{
    extern __shared__ __align__(16) uint32_t smp[];
    const int t = threadIdx.x;
    const int lane = t & 31, wid = t >> 5;
    const int wm = wid & 3, wn = wid >> 2;
    const size_t bm = (size_t)blockIdx.y * 128;
    const int bn = blockIdx.x * 128;

    float acc[2][8][4];
    #pragma unroll
    for (int i = 0; i < 2; i++)
        #pragma unroll
        for (int j = 0; j < 8; j++)
            #pragma unroll
            for (int k = 0; k < 4; k++) acc[i][j][k] = 0.f;

    gemm_hilo_core<false>(smp, h3T_hi_g, h3T_hi_g, bm,
                          protoT_hi_g, protoT_lo_g, bn, 512, acc, t);

    // ---- epilogue: distances + min over pos ----
    unsigned* minred = (unsigned*)smp;           // [8][128]
    float* pps = (float*)(smp + 1024);           // [128]
    for (int i = t; i < 1024; i += 256) minred[i] = INFBITS;
    if (t < 128) pps[t] = pp_g[bn + t];
    __syncthreads();

    const int img0 = (int)(bm / 25);

    float x2v[2][2];
    #pragma unroll
    for (int ms = 0; ms < 2; ms++) {
        int r0 = wm * 32 + ms * 16 + (lane >> 2);
        x2v[ms][0] = x2_g[bm + r0];
        x2v[ms][1] = x2_g[bm + r0 + 8];
    }

    #pragma unroll
    for (int ms = 0; ms < 2; ms++) {
        int r0 = wm * 32 + ms * 16 + (lane >> 2);
        int slot0 = (int)((bm + r0) / 25) - img0;
        int slot1 = (int)((bm + r0 + 8) / 25) - img0;
        #pragma unroll
        for (int nt = 0; nt < 8; nt++) {
            int ncol = wn * 64 + nt * 8 + 2 * (lane & 3);
            float p0 = pps[ncol], p1 = pps[ncol + 1];
            float d00 = fmaxf(x2v[ms][0] - 2.f * acc[ms][nt][0] + p0, 0.f);
            float d01 = fmaxf(x2v[ms][0] - 2.f * acc[ms][nt][1] + p1, 0.f);
            float d10 = fmaxf(x2v[ms][1] - 2.f * acc[ms][nt][2] + p0, 0.f);
            float d11 = fmaxf(x2v[ms][1] - 2.f * acc[ms][nt][3] + p1, 0.f);
            atomicMin(&minred[slot0 * 128 + ncol], __float_as_uint(d00));
            atomicMin(&minred[slot0 * 128 + ncol + 1], __float_as_uint(d01));
            atomicMin(&minred[slot1 * 128 + ncol], __float_as_uint(d10));
            atomicMin(&minred[slot1 * 128 + ncol + 1], __float_as_uint(d11));
        }
    }
    __syncthreads();

    for (int i = t; i < 1024; i += 256) {
        unsigned v = minred[i];
        if (v != INFBITS) {
            int slot = i >> 7, col = i & 127;
            atomicMin((unsigned*)&minD[(size_t)(img0 + slot) * 512 + bn + col], v);
        }
    }
}

// up GEMM (2-pass): C[4096x6400] = z * wupPT, BN+relu, col n = pos*256+c
__global__ __launch_bounds__(256, 2) void up_gemm_kernel(
    const float* __restrict__ bup,
    const float* __restrict__ gup, const float* __restrict__ btup)
{
    extern __shared__ __align__(16) uint32_t smp[];
    const int t = threadIdx.x;
    const int lane = t & 31, wid = t >> 5;
    const int wm = wid & 3, wn = wid >> 2;
    const size_t bm = (size_t)blockIdx.y * 128;
    const int bn = blockIdx.x * 128;

    float acc[2][8][4];
    #pragma unroll
    for (int i = 0; i < 2; i++)
        #pragma unroll
        for (int j = 0; j < 8; j++)
            #pragma unroll
            for (int k = 0; k < 4; k++) acc[i][j][k] = 0.f;

    gemm_hilo_core<false>(smp, z_hi_g, z_hi_g, bm,
                          wupPT_hi_g, wupPT_lo_g, bn, 6400, acc, t);

    const float rsc = rsqrtf(1.f + BEPS);
    #pragma unroll
    for (int ms = 0; ms < 2; ms++)
        #pragma unroll
        for (int nt = 0; nt < 8; nt++) {
            size_t row0 = bm + wm * 32 + ms * 16 + (lane >> 2);
            int col0 = bn + wn * 64 + nt * 8 + 2 * (lane & 3);
            int c0 = col0 & 255, c1 = (col0 + 1) & 255;
            float s0 = gup[c0] * rsc, s1 = gup[c1] * rsc;
            float bi0 = bup[c0] * s0 + btup[c0];
            float bi1 = bup[c1] * s1 + btup[c1];
            *(float2*)&up2_g[row0 * 6400 + col0] =
                make_float2(fmaxf(acc[ms][nt][0] * s0 + bi0, 0.f),
                            fmaxf(acc[ms][nt][1] * s1 + bi1, 0.f));
            *(float2*)&up2_g[(row0 + 8) * 6400 + col0] =
                make_float2(fmaxf(acc[ms][nt][2] * s0 + bi0, 0.f),
                            fmaxf(acc[ms][nt][3] * s1 + bi1, 0.f));
        }
}

// ---------------------------------------------------------------------------
// g GEMM (2-pass, in-loop cvt; A hi only): G[102400x144] = up2 * wd1
// ---------------------------------------------------------------------------
#define AS_STRIDE 36
#define GBS_STRIDE 152
__global__ __launch_bounds__(512, 1) void g_gemm_kernel(const float* __restrict__ wd1)
{
    __shared__ float As[128 * AS_STRIDE];
    __shared__ float Bs[32 * GBS_STRIDE];

    const int t = threadIdx.x;
    const int lane = t & 31, wid = t >> 5;
    const int wm = wid & 7, wn = wid >> 3;
    const int bm = blockIdx.x * 128;

    float acc[9][4];
    #pragma unroll
    for (int j = 0; j < 9; j++)
        #pragma unroll
        for (int k = 0; k < 4; k++) acc[j][k] = 0.f;

    const int ar = t >> 2, ak = (t & 3) * 8;

    for (int k0 = 0; k0 < 256; k0 += 32) {
        const float* asrc = &up2_g[(size_t)(bm + ar) * 256 + k0 + ak];
        float4 av0 = *(const float4*)asrc;
        float4 av1 = *(const float4*)(asrc + 4);
        float bvals[9];
        #pragma unroll
        for (int j = 0; j < 9; j++) {
            int i = t + j * 512;
            int row = i / 144, col = i - row * 144;
            bvals[j] = wd1[(size_t)(k0 + row) * 144 + col];
        }
        __syncthreads();
        *(float4*)&As[ar * AS_STRIDE + ak]     = av0;
        *(float4*)&As[ar * AS_STRIDE + ak + 4] = av1;
        #pragma unroll
        for (int j = 0; j < 9; j++) {
            int i = t + j * 512;
            int row = i / 144, col = i - row * 144;
            Bs[row * GBS_STRIDE + col] = bvals[j];
        }
        __syncthreads();

        #pragma unroll
        for (int ks = 0; ks < 4; ks++) {
            const int col = ks * 8 + (lane & 3);
            uint32_t ah[4];
            {
                int mb = wm * 16 + (lane >> 2);
                ah[0] = cvt_hi(As[mb * AS_STRIDE + col]);
                ah[1] = cvt_hi(As[(mb + 8) * AS_STRIDE + col]);
                ah[2] = cvt_hi(As[mb * AS_STRIDE + col + 4]);
                ah[3] = cvt_hi(As[(mb + 8) * AS_STRIDE + col + 4]);
            }
            const int row = ks * 8 + (lane & 3);
            #pragma unroll
            for (int nt = 0; nt < 9; nt++) {
                int nb = wn * 72 + nt * 8 + (lane >> 2);
                float y0 = Bs[row * GBS_STRIDE + nb];
                float y1 = Bs[(row + 4) * GBS_STRIDE + nb];
                uint32_t bh[2], bl[2];
                cvt_hilo(y0, bh[0], bl[0]);
                cvt_hilo(y1, bh[1], bl[1]);
                mma_tf32(acc[nt], ah, bh);
                mma_tf32(acc[nt], ah, bl);
            }
        }
    }

    #pragma unroll
    for (int nt = 0; nt < 9; nt++) {
        int row0 = bm + wm * 16 + (lane >> 2);
        int col0 = wn * 72 + nt * 8 + 2 * (lane & 3);
        *(float2*)&G_g[(size_t)row0 * 144 + col0] = make_float2(acc[nt][0], acc[nt][1]);
        *(float2*)&G_g[(size_t)(row0 + 8) * 144 + col0] = make_float2(acc[nt][2], acc[nt][3]);
    }
}

// ---------------------------------------------------------------------------
// softmax over minD -> w_g
// ---------------------------------------------------------------------------
__global__ __launch_bounds__(512) void softmax_kernel(const float* __restrict__ minD)
{
    __shared__ float red[32];
    const int b = blockIdx.x;
    const int t = threadIdx.x;
    const int lane = t & 31, wid = t >> 5;

    float m = minD[(size_t)b * 512 + t];
    float a = -m;
    float v = a;
    #pragma unroll
    for (int off = 16; off; off >>= 1) v = fmaxf(v, __shfl_xor_sync(0xffffffffu, v, off));
    if (!lane) red[wid] = v;
    __syncthreads();
    if (t == 0) {
        float r = red[0];
        for (int i = 1; i < 16; i++) r = fmaxf(r, red[i]);
        red[16] = r;
    }
    __syncthreads();
    float amax = red[16];
    float e = expf(a - amax);
    float sv = e;
    #pragma unroll
    for (int off = 16; off; off >>= 1) sv += __shfl_xor_sync(0xffffffffu, sv, off);
    __syncthreads();
    if (!lane) red[wid] = sv;
    __syncthreads();
    if (t == 0) {
        float r = 0.f;
        for (int i = 0; i < 16; i++) r += red[i];
        red[16] = r;
    }
    __syncthreads();
    w_g[(size_t)b * 512 + t] = e * (1.f / red[16]);
}

// ---------------------------------------------------------------------------
// z GEMM (FFMA f32x2): z = w * proto; epilogue emits z hi only
// ---------------------------------------------------------------------------
__global__ __launch_bounds__(256) void z_gemm_kernel(const float* __restrict__ proto)
{
    __shared__ __align__(16) float As2[16][128];
    __shared__ __align__(16) float Bs2[16][64];
    const int bn = blockIdx.x * 64;
    const int bm = blockIdx.y * 128;
    const int t = threadIdx.x;
    const int tx = t & 15, ty = t >> 4;

    unsigned long long acc[4][4];
    #pragma unroll
    for (int i = 0; i < 4; i++)
        #pragma unroll
        for (int j = 0; j < 4; j++) acc[i][j] = 0ull;

    for (int k0 = 0; k0 < 512; k0 += 16) {
        #pragma unroll
        for (int s = t; s < 512; s += 256) {
            int r = s >> 2, kq = (s & 3) << 2;
            float4 v = *(const float4*)&w_g[(size_t)(bm + r) * 512 + k0 + kq];
            As2[kq + 0][r] = v.x; As2[kq + 1][r] = v.y;
            As2[kq + 2][r] = v.z; As2[kq + 3][r] = v.w;
        }
        {
            int kk = t >> 4, n4 = (t & 15) << 2;
            *(float4*)&Bs2[kk][n4] = *(const float4*)&proto[(size_t)(k0 + kk) * 256 + bn + n4];
        }
        __syncthreads();
        #pragma unroll
        for (int kk = 0; kk < 16; kk++) {
            ulonglong2 a01 = *(const ulonglong2*)&As2[kk][ty * 8];
            ulonglong2 a23 = *(const ulonglong2*)&As2[kk][ty * 8 + 4];
            float4 bv = *(const float4*)&Bs2[kk][tx * 4];
            unsigned long long bd0 = pack2(bv.x, bv.x), bd1 = pack2(bv.y, bv.y);
            unsigned long long bd2 = pack2(bv.z, bv.z), bd3 = pack2(bv.w, bv.w);
            acc[0][0] = ffma2(a01.x, bd0, acc[0][0]); acc[0][1] = ffma2(a01.x, bd1, acc[0][1]);
            acc[0][2] = ffma2(a01.x, bd2, acc[0][2]); acc[0][3] = ffma2(a01.x, bd3, acc[0][3]);
            acc[1][0] = ffma2(a01.y, bd0, acc[1][0]); acc[1][1] = ffma2(a01.y, bd1, acc[1][1]);
            acc[1][2] = ffma2(a01.y, bd2, acc[1][2]); acc[1][3] = ffma2(a01.y, bd3, acc[1][3]);
            acc[2][0] = ffma2(a23.x, bd0, acc[2][0]); acc[2][1] = ffma2(a23.x, bd1, acc[2][1]);
            acc[2][2] = ffma2(a23.x, bd2, acc[2][2]); acc[2][3] = ffma2(a23.x, bd3, acc[2][3]);
            acc[3][0] = ffma2(a23.y, bd0, acc[3][0]); acc[3][1] = ffma2(a23.y, bd1, acc[3][1]);
            acc[3][2] = ffma2(a23.y, bd2, acc[3][2]); acc[3][3] = ffma2(a23.y, bd3, acc[3][3]);
        }
        __syncthreads();
    }

    #pragma unroll
    for (int mp = 0; mp < 4; mp++) {
        int m0 = bm + ty * 8 + mp * 2;
        float2 f0 = unpack2(acc[mp][0]), f1 = unpack2(acc[mp][1]);
        float2 f2 = unpack2(acc[mp][2]), f3 = unpack2(acc[mp][3]);
        float rows[2][4] = {{f0.x, f1.x, f2.x, f3.x}, {f0.y, f1.y, f2.y, f3.y}};
        #pragma unroll
        for (int rr = 0; rr < 2; rr++) {
            uint4 hi;
            hi.x = cvt_hi(rows[rr][0]);
            hi.y = cvt_hi(rows[rr][1]);
            hi.z = cvt_hi(rows[rr][2]);
            hi.w = cvt_hi(rows[rr][3]);
            size_t idx = (size_t)(m0 + rr) * 256 + bn + tx * 4;
            *(uint4*)&z_hi_g[idx] = hi;
        }
    }
}

// ---------------------------------------------------------------------------
// dec2: d1 = scatter(G)+BN+relu, then d2, d3. 2 images per block.
// ---------------------------------------------------------------------------
__global__ __launch_bounds__(256) void dec2_kernel(
    const float* __restrict__ bd1,
    const float* __restrict__ gd1, const float* __restrict__ btd1,
    const float* __restrict__ wd2, const float* __restrict__ bd2,
    const float* __restrict__ gd2, const float* __restrict__ btd2,
    const float* __restrict__ wd3, const float* __restrict__ bd3,
    float* __restrict__ out)
{
    extern __shared__ float sm[];
    float* Gs   = sm;                 // 2 * 3600
    float* d1s  = Gs + 7200;          // 2 * 784
    float* d2s  = d1s + 1568;         // 2 * 1568
    float* wd2s = d2s + 3136;         // 1152
    float* wd3s = wd2s + 1152;        // 72

    const int t = threadIdx.x;
    const int b0 = blockIdx.x * 2;
    const float rs = rsqrtf(1.f + BEPS);

    for (int i = t; i < 7200; i += 256) Gs[i] = G_g[(size_t)b0 * 3600 + i];
    for (int i = t; i < 1152; i += 256) wd2s[i] = wd2[i];
    if (t < 72) wd3s[t] = wd3[t];
    __syncthreads();

    for (int idx = t; idx < 1568; idx += 256) {
        int img = idx / 784, r = idx - img * 784;
        int o = r / 49, pos = r - o * 49;
        int oi = pos / 7, oj = pos % 7;
        int y0 = max(oi - 2, 0), y1 = min(oi, 4);
        int x0 = max(oj - 2, 0), x1 = min(oj, 4);
        float sum = 0.f;
        const float* Gb = &Gs[img * 3600];
        for (int y = y0; y <= y1; y++) {
            int ki = oi - y;
            for (int xx = x0; xx <= x1; xx++) {
                int kj = oj - xx;
                sum += Gb[(y * 5 + xx) * 144 + o * 9 + ki * 3 + kj];
            }
        }
        float s = gd1[o] * rs;
        d1s[img * 784 + o * 49 + pos] = fmaxf((sum + bd1[o]) * s + btd1[o], 0.f);
    }
    __syncthreads();

    if (t < 196) {
        float acc2[2][8];
        #pragma unroll
        for (int a = 0; a < 2; a++)
            #pragma unroll
            for (int o = 0; o < 8; o++) acc2[a][o] = 0.f;
        int i = t / 14, j = t % 14;
        int ylo = i / 2, yhi = min((i + 1) / 2, 6);
        int xlo = j / 2, xhi = min((j + 1) / 2, 6);
        for (int c = 0; c < 16; c++) {
            for (int y = ylo; y <= yhi; y++) {
                int ki = i - 2 * y + 1;
                for (int xx = xlo; xx <= xhi; xx++) {
                    int kj = j - 2 * xx + 1;
                    float u0 = d1s[0 * 784 + c * 49 + y * 7 + xx];
                    float u1 = d1s[1 * 784 + c * 49 + y * 7 + xx];
                    #pragma unroll
                    for (int o = 0; o < 8; o++) {
                        float wv = wd2s[((c * 8 + o) * 3 + ki) * 3 + kj];
                        acc2[0][o] += u0 * wv;
                        acc2[1][o] += u1 * wv;
                    }
                }
            }
        }
        #pragma unroll
        for (int o = 0; o < 8; o++) {
            float s = gd2[o] * rs;
            float bias = bd2[o] * s + btd2[o];
            #pragma unroll
            for (int a = 0; a < 2; a++)
                d2s[a * 1568 + o * 196 + t] = fmaxf(acc2[a][o] * s + bias, 0.f);
        }
    }
    __syncthreads();

    const float bb3 = bd3[0];
    for (int idx = t; idx < 1568; idx += 256) {
        int a = idx / 784, p = idx - a * 784, i = p / 28, j = p % 28;
        int ylo = i / 2, yhi = min((i + 1) / 2, 13);
        int xlo = j / 2, xhi = min((j + 1) / 2, 13);
        float acc3 = bb3;
        for (int c = 0; c < 8; c++) {
            for (int y = ylo; y <= yhi; y++) {
                int ki = i - 2 * y + 1;
                for (int xx = xlo; xx <= xhi; xx++) {
                    int kj = j - 2 * xx + 1;
                    acc3 += d2s[a * 1568 + c * 196 + y * 14 + xx] * wd3s[c * 9 + ki * 3 + kj];
                }
            }
        }
        out[(size_t)(b0 + a) * 784 + p] = 1.f / (1.f + expf(-acc3));
    }
}

// ---------------------------------------------------------------------------
extern "C" void kernel_launch(void* const* d_in, const int* in_sizes, int n_in,
                              void* d_out, int out_size)
{
    const float* x     = (const float*)d_in[0];
    const float* w1    = (const float*)d_in[1];
    const float* b1    = (const float*)d_in[2];
    const float* w2    = (const float*)d_in[3];
    const float* b2    = (const float*)d_in[4];
    const float* g2    = (const float*)d_in[5];
    const float* bt2   = (const float*)d_in[6];
    const float* w3    = (const float*)d_in[7];
    const float* b3    = (const float*)d_in[8];
    const float* proto = (const float*)d_in[9];
    const float* wup   = (const float*)d_in[10];
    const float* bup   = (const float*)d_in[11];
    const float* gup   = (const float*)d_in[12];
    const float* btup  = (const float*)d_in[13];
    const float* wd1   = (const float*)d_in[14];
    const float* bd1   = (const float*)d_in[15];
    const float* gd1   = (const float*)d_in[16];
    const float* btd1  = (const float*)d_in[17];
    const float* wd2   = (const float*)d_in[18];
    const float* bd2   = (const float*)d_in[19];
    const float* gd2   = (const float*)d_in[20];
    const float* btd2  = (const float*)d_in[21];
    const float* wd3   = (const float*)d_in[22];
    const float* bd3   = (const float*)d_in[23];

    float* out  = (float*)d_out;                 // (4096,1,28,28)
    float* minD = out + (size_t)NB * 784;        // (4096,512)

    prep_kernel<<<256, 256>>>(proto, w3, wup);
    enc12_kernel<<<NB, 128>>>(x, w1, b1, w2, b2, g2, bt2);
    conv3_kernel<<<NB, 256>>>(b3);
    x2_kernel<<<(NB * 25) / 8, 256>>>();
    init_mind_kernel<<<NB, 512>>>(minD);

    cudaFuncSetAttribute(xp_gemm_kernel, cudaFuncAttributeMaxDynamicSharedMemorySize, PIPE_SMEM);
    dim3 gx(512 / 128, (NB * 25) / 128);         // (4, 800)
    xp_gemm_kernel<<<gx, 256, PIPE_SMEM>>>(minD);

    softmax_kernel<<<NB, 512>>>(minD);

    dim3 gz(256 / 64, NB / 128);
    z_gemm_kernel<<<gz, 256>>>(proto);

    cudaFuncSetAttribute(up_gemm_kernel, cudaFuncAttributeMaxDynamicSharedMemorySize, PIPE_SMEM);
    dim3 gu(6400 / 128, NB / 128);               // (50, 32)
    up_gemm_kernel<<<gu, 256, PIPE_SMEM>>>(bup, gup, btup);

    g_gemm_kernel<<<(NB * 25) / 128, 512>>>(wd1);   // 800 blocks

    size_t smem2 = (size_t)(7200 + 1568 + 3136 + 1152 + 72) * sizeof(float); // 52,512 B
    cudaFuncSetAttribute(dec2_kernel, cudaFuncAttributeMaxDynamicSharedMemorySize, (int)smem2);
    dec2_kernel<<<NB / 2, 256, smem2>>>(bd1, gd1, btd1,
                                        wd2, bd2, gd2, btd2,
                                        wd3, bd3, out);
}

// round 15
// speedup vs baseline: 1.4917x; 1.2263x over previous
#include <cuda_runtime.h>
#include <math.h>
#include <stdint.h>

#define BEPS 1e-5f
#define NB 4096
#define INFBITS 0x7F800000u

// ---------------- scratch (allocation-free) ----------------
__device__ float h2_g[NB * 784];
__device__ float h3T_g[(size_t)NB * 25 * 256];        // [(b*25+pos)][d]
__device__ uint32_t h3T_hi_g[(size_t)NB * 25 * 256];  // tf32 hi
__device__ float x2_g[(size_t)NB * 25];               // per-row squared norm
__device__ float w_g[NB * 512];
__device__ uint32_t z_hi_g[NB * 256];
__device__ float up2_g[(size_t)NB * 6400];            // [(b*25+pos)][c]
__device__ float G_g[(size_t)NB * 25 * 144];          // [(b*25+pos)][o*9+tap]
__device__ float protoT_g[256 * 512];                 // [d][p] raw (z_gemm B)
__device__ uint32_t protoT_hi_g[256 * 512];           // [k][n] tf32 hi
__device__ uint32_t wupPT_hi_g[256 * 6400];           // [k][pos*256+c]
__device__ float pp_g[512];                           // sum_d proto^2
__device__ float w3t_g[256 * 144];                    // [(c*9+tap)][oc]

// ---------------- packed fp32x2 helpers ----------------
static __device__ __forceinline__ unsigned long long ffma2(
    unsigned long long a, unsigned long long b, unsigned long long c) {
    unsigned long long d;
    asm("fma.rn.f32x2 %0, %1, %2, %3;" : "=l"(d) : "l"(a), "l"(b), "l"(c));
    return d;
}
static __device__ __forceinline__ unsigned long long pack2(float x, float y) {
    unsigned long long r;
    asm("mov.b64 %0, {%1, %2};" : "=l"(r) : "f"(x), "f"(y));
    return r;
}
static __device__ __forceinline__ float2 unpack2(unsigned long long v) {
    float2 r;
    asm("mov.b64 {%0, %1}, %2;" : "=f"(r.x), "=f"(r.y) : "l"(v));
    return r;
}

// ---------------- tf32 helpers ----------------
static __device__ __forceinline__ uint32_t cvt_hi(float x) {
    uint32_t h;
    asm("cvt.rna.tf32.f32 %0, %1;" : "=r"(h) : "f"(x));
    return h;
}
static __device__ __forceinline__ void mma_tf32(float* c, const uint32_t* a, const uint32_t* b) {
    asm volatile(
        "mma.sync.aligned.m16n8k8.row.col.f32.tf32.tf32.f32 "
        "{%0,%1,%2,%3}, {%4,%5,%6,%7}, {%8,%9}, {%0,%1,%2,%3};"
        : "+f"(c[0]), "+f"(c[1]), "+f"(c[2]), "+f"(c[3])
        : "r"(a[0]), "r"(a[1]), "r"(a[2]), "r"(a[3]), "r"(b[0]), "r"(b[1]));
}

// ---------------- cp.async helpers ----------------
static __device__ __forceinline__ uint32_t smem_u32(const void* p) {
    uint32_t a;
    asm("{ .reg .u64 t; cvta.to.shared.u64 t, %1; cvt.u32.u64 %0, t; }" : "=r"(a) : "l"(p));
    return a;
}
#define CPASYNC16(dst, src) \
    asm volatile("cp.async.cg.shared.global [%0], [%1], 16;" :: "r"(dst), "l"(src) : "memory")
#define CPCOMMIT() asm volatile("cp.async.commit_group;" ::: "memory")
#define CPWAIT1() asm volatile("cp.async.wait_group 1;" ::: "memory")
#define CPWAIT0() asm volatile("cp.async.wait_group 0;" ::: "memory")

// ---------------------------------------------------------------------------
// prep: tf32 hi conversions + transposes + proto norms
// ---------------------------------------------------------------------------
__global__ void prep_kernel(const float* __restrict__ proto,
                            const float* __restrict__ w3,
                            const float* __restrict__ wup)
{
    int stride = gridDim.x * blockDim.x;
    int tid = blockIdx.x * blockDim.x + threadIdx.x;
    for (int i = tid; i < 512 * 256; i += stride) {
        int d = i >> 9, p = i & 511;
        float v = proto[p * 256 + d];
        protoT_g[i] = v;
        protoT_hi_g[i] = cvt_hi(v);
    }
    for (int p = tid; p < 512; p += stride) {
        float s = 0.f;
        for (int d = 0; d < 256; d++) {
            float v = proto[p * 256 + d];
            s += v * v;
        }
        pp_g[p] = s;
    }
    for (int i = tid; i < 256 * 144; i += stride) {
        int o = i & 255, ct = i >> 8;
        int c = ct / 9, tap = ct - c * 9;
        w3t_g[i] = w3[o * 144 + c * 9 + tap];
    }
    for (int i = tid; i < 256 * 6400; i += stride) {
        int k = i / 6400, rr = i % 6400;
        int pos = rr >> 8, c = rr & 255;
        wupPT_hi_g[i] = cvt_hi(wup[(size_t)k * 6400 + c * 25 + pos]);
    }
}

// ---------------------------------------------------------------------------
// init minD to +inf
// ---------------------------------------------------------------------------
__global__ __launch_bounds__(512) void init_mind_kernel(float* __restrict__ minD)
{
    minD[(size_t)blockIdx.x * 512 + threadIdx.x] = __uint_as_float(INFBITS);
}

// ---------------------------------------------------------------------------
// enc12: conv1 + conv2, one block per image
// ---------------------------------------------------------------------------
__global__ __launch_bounds__(128) void enc12_kernel(
    const float* __restrict__ x,
    const float* __restrict__ w1, const float* __restrict__ b1,
    const float* __restrict__ w2, const float* __restrict__ b2,
    const float* __restrict__ g2, const float* __restrict__ bt2)
{
    __shared__ float xs[784];
    __shared__ float h1s[8 * 196];
    const int b = blockIdx.x;
    const int t = threadIdx.x;

    const float* xb = x + b * 784;
    for (int i = t; i < 784; i += 128) xs[i] = xb[i];
    __syncthreads();

    for (int idx = t; idx < 1568; idx += 128) {
        int o = idx / 196, r = idx % 196, i = r / 14, j = r % 14;
        float acc = b1[o];
        #pragma unroll
        for (int ky = 0; ky < 3; ky++) {
            int y = 2 * i - 1 + ky;
            if ((unsigned)y >= 28u) continue;
            #pragma unroll
            for (int kx = 0; kx < 3; kx++) {
                int xx = 2 * j - 1 + kx;
                if ((unsigned)xx >= 28u) continue;
                acc += xs[y * 28 + xx] * w1[o * 9 + ky * 3 + kx];
            }
        }
        h1s[idx] = fmaxf(acc, 0.f);
    }
    __syncthreads();

    const float rs = rsqrtf(1.f + BEPS);
    for (int idx = t; idx < 784; idx += 128) {
        int o = idx / 49, r = idx % 49, i = r / 7, j = r % 7;
        float acc = 0.f;
        for (int c = 0; c < 8; c++) {
            #pragma unroll
            for (int ky = 0; ky < 3; ky++) {
                int y = 2 * i - 1 + ky;
                if ((unsigned)y >= 14u) continue;
                #pragma unroll
                for (int kx = 0; kx < 3; kx++) {
                    int xx = 2 * j - 1 + kx;
                    if ((unsigned)xx >= 14u) continue;
                    acc += h1s[c * 196 + y * 14 + xx] * w2[((o * 8 + c) * 3 + ky) * 3 + kx];
                }
            }
        }
        float s = g2[o] * rs;
        h2_g[b * 784 + idx] = fmaxf((acc + b2[o]) * s + bt2[o], 0.f);
    }
}

// ---------------------------------------------------------------------------
// conv3: 16->256 k3 s1 p0, 7->5; writes h3T raw + tf32 hi
// ---------------------------------------------------------------------------
__global__ __launch_bounds__(256, 2) void conv3_kernel(const float* __restrict__ b3)
{
    __shared__ float h2s[784];
    const int b = blockIdx.x;
    const int t = threadIdx.x;

    for (int i = t; i < 784; i += 256) h2s[i] = h2_g[b * 784 + i];
    __syncthreads();

    float acc[25];
    #pragma unroll
    for (int p = 0; p < 25; p++) acc[p] = 0.f;

    for (int c = 0; c < 16; c++) {
        float w[9];
        #pragma unroll
        for (int tap = 0; tap < 9; tap++) w[tap] = w3t_g[(c * 9 + tap) * 256 + t];
        float h[49];
        #pragma unroll
        for (int i = 0; i < 49; i++) h[i] = h2s[c * 49 + i];
        #pragma unroll
        for (int ky = 0; ky < 3; ky++)
            #pragma unroll
            for (int kx = 0; kx < 3; kx++) {
                float wv = w[ky * 3 + kx];
                #pragma unroll
                for (int i = 0; i < 5; i++)
                    #pragma unroll
                    for (int j = 0; j < 5; j++)
                        acc[i * 5 + j] += wv * h[(i + ky) * 7 + (j + kx)];
            }
    }
    float bb = b3[t];
    #pragma unroll
    for (int p = 0; p < 25; p++) {
        float v = fmaxf(acc[p] + bb, 0.f);
        size_t idx = ((size_t)b * 25 + p) * 256 + t;
        h3T_g[idx] = v;
        h3T_hi_g[idx] = cvt_hi(v);
    }
}

// ---------------------------------------------------------------------------
// x2: per-row squared norm of h3T (warp per row)
// ---------------------------------------------------------------------------
__global__ __launch_bounds__(256) void x2_kernel()
{
    const int wid = threadIdx.x >> 5, lane = threadIdx.x & 31;
    const size_t row = (size_t)blockIdx.x * 8 + wid;
    const float* r = &h3T_g[row * 256];
    float s = 0.f;
    #pragma unroll
    for (int j = 0; j < 8; j++) {
        float v = r[lane + 32 * j];
        s += v * v;
    }
    #pragma unroll
    for (int off = 16; off; off >>= 1) s += __shfl_xor_sync(0xffffffffu, s, off);
    if (!lane) x2_g[row] = s;
}

// ===========================================================================
// 1-pass TF32 GEMM core (pure hi operands, pre-converted).
// Block 128x128, 8 warps (4m x 2n), warp tile 32x64, k-chunk 16, 2 stages.
// ===========================================================================
#define ASTR 20
#define BSTR 136
#define ASTG16 (128 * ASTR)
#define BSTG16 (16 * BSTR)
#define OFF_BH (2 * ASTG16)
#define PIPE_SMEM ((2 * ASTG16 + 2 * BSTG16) * 4)   // 37,888 bytes

static __device__ __forceinline__ void gemm_hi_core(
    uint32_t* smp,
    const uint32_t* __restrict__ gAh, size_t arow0,
    const uint32_t* __restrict__ gBh, size_t bcol0,
    int ldb, float acc[2][8][4], int t)
{
    const int lane = t & 31, wid = t >> 5;
    const int wm = wid & 3, wn = wid >> 2;

    const int ar = t >> 1, ak = (t & 1) * 8;
    const int br = t >> 4, bn8 = (t & 15) * 8;
    const uint32_t smb = smem_u32(smp);
    const uint32_t sAh = smb + (uint32_t)(ar * ASTR + ak) * 4;
    const uint32_t sBh = smb + (uint32_t)(OFF_BH + br * BSTR + bn8) * 4;
    const uint32_t* gA_h = gAh + (arow0 + ar) * 256 + ak;
    const uint32_t* gB_h = gBh + (size_t)br * ldb + bcol0 + bn8;

    CPASYNC16(sAh, gA_h);          CPASYNC16(sAh + 16, gA_h + 4);
    CPASYNC16(sBh, gB_h);          CPASYNC16(sBh + 16, gB_h + 4);
    CPCOMMIT();

    for (int c = 0; c < 16; c++) {
        if (c < 15) {
            const int k0 = (c + 1) * 16;
            const uint32_t st = (uint32_t)((c + 1) & 1);
            uint32_t dAh = sAh + st * ASTG16 * 4;
            uint32_t dBh = sBh + st * BSTG16 * 4;
            CPASYNC16(dAh, gA_h + k0);      CPASYNC16(dAh + 16, gA_h + k0 + 4);
            CPASYNC16(dBh, gB_h + (size_t)k0 * ldb);
            CPASYNC16(dBh + 16, gB_h + (size_t)k0 * ldb + 4);
            CPCOMMIT();
            CPWAIT1();
        } else {
            CPWAIT0();
        }
        __syncthreads();

        const uint32_t st = (uint32_t)(c & 1);
        const uint32_t* Ah = smp + st * ASTG16;
        const uint32_t* Bh = smp + OFF_BH + st * BSTG16;

        #pragma unroll
        for (int ks = 0; ks < 2; ks++) {
            const int col = ks * 8 + (lane & 3);
            uint32_t ah[2][4];
            #pragma unroll
            for (int ms = 0; ms < 2; ms++) {
                int mb = wm * 32 + ms * 16 + (lane >> 2);
                ah[ms][0] = Ah[mb * ASTR + col];
                ah[ms][1] = Ah[(mb + 8) * ASTR + col];
                ah[ms][2] = Ah[mb * ASTR + col + 4];
                ah[ms][3] = Ah[(mb + 8) * ASTR + col + 4];
            }
            const int row = ks * 8 + (lane & 3);
            #pragma unroll
            for (int nt = 0; nt < 8; nt++) {
                int nb = wn * 64 + nt * 8 + (lane >> 2);
                uint32_t bh[2];
                bh[0] = Bh[row * BSTR + nb];
                bh[1] = Bh[(row + 4) * BSTR + nb];
                #pragma unroll
                for (int ms = 0; ms < 2; ms++)
                    mma_tf32(acc[ms][nt], ah[ms], bh);
            }
        }
        __syncthreads();
    }
}

// xp GEMM (1-pass) + fused distance/min: minD[b][p] = min_pos relu(x2 - 2*xp + pp)
__global__ __launch_bounds__(256, 2) void xp_gemm_kernel(float* __restrict__ minD)
{
    extern __shared__ __align__(16) uint32_t smp[];
    const int t = threadIdx.x;
    const int lane = t & 31, wid = t >> 5;
    const int wm = wid & 3, wn = wid >> 2;
    const size_t bm = (size_t)blockIdx.y * 128;
    const int bn = blockIdx.x * 128;

    float acc[2][8][4];
    #pragma unroll
    for (int i = 0; i < 2; i++)
        #pragma unroll
        for (int j = 0; j < 8; j++)
            #pragma unroll
            for (int k = 0; k < 4; k++) acc[i][j][k] = 0.f;

    gemm_hi_core(smp, h3T_hi_g, bm, protoT_hi_g, bn, 512, acc, t);

    // ---- epilogue: distances + min over pos ----
    unsigned* minred = (unsigned*)smp;           // [8][128]
    float* pps = (float*)(smp + 1024);           // [128]
    for (int i = t; i < 1024; i += 256) minred[i] = INFBITS;
    if (t < 128) pps[t] = pp_g[bn + t];
    __syncthreads();

    const int img0 = (int)(bm / 25);

    float x2v[2][2];
    #pragma unroll
    for (int ms = 0; ms < 2; ms++) {
        int r0 = wm * 32 + ms * 16 + (lane >> 2);
        x2v[ms][0] = x2_g[bm + r0];
        x2v[ms][1] = x2_g[bm + r0 + 8];
    }

    #pragma unroll
    for (int ms = 0; ms < 2; ms++) {
        int r0 = wm * 32 + ms * 16 + (lane >> 2);
        int slot0 = (int)((bm + r0) / 25) - img0;
        int slot1 = (int)((bm + r0 + 8) / 25) - img0;
        #pragma unroll
        for (int nt = 0; nt < 8; nt++) {
            int ncol = wn * 64 + nt * 8 + 2 * (lane & 3);
            float p0 = pps[ncol], p1 = pps[ncol + 1];
            float d00 = fmaxf(x2v[ms][0] - 2.f * acc[ms][nt][0] + p0, 0.f);
            float d01 = fmaxf(x2v[ms][0] - 2.f * acc[ms][nt][1] + p1, 0.f);
            float d10 = fmaxf(x2v[ms][1] - 2.f * acc[ms][nt][2] + p0, 0.f);
            float d11 = fmaxf(x2v[ms][1] - 2.f * acc[ms][nt][3] + p1, 0.f);
            atomicMin(&minred[slot0 * 128 + ncol], __float_as_uint(d00));
            atomicMin(&minred[slot0 * 128 + ncol + 1], __float_as_uint(d01));
            atomicMin(&minred[slot1 * 128 + ncol], __float_as_uint(d10));
            atomicMin(&minred[slot1 * 128 + ncol + 1], __float_as_uint(d11));
        }
    }
    __syncthreads();

    for (int i = t; i < 1024; i += 256) {
        unsigned v = minred[i];
        if (v != INFBITS) {
            int slot = i >> 7, col = i & 127;
            atomicMin((unsigned*)&minD[(size_t)(img0 + slot) * 512 + bn + col], v);
        }
    }
}

// up GEMM (1-pass): C[4096x6400] = z * wupPT, BN+relu, col n = pos*256+c
__global__ __launch_bounds__(256, 2) void up_gemm_kernel(
    const float* __restrict__ bup,
    const float* __restrict__ gup, const float* __restrict__ btup)
{
    extern __shared__ __align__(16) uint32_t smp[];
    const int t = threadIdx.x;
    const int lane = t & 31, wid = t >> 5;
    const int wm = wid & 3, wn = wid >> 2;
    const size_t bm = (size_t)blockIdx.y * 128;
    const int bn = blockIdx.x * 128;

    float acc[2][8][4];
    #pragma unroll
    for (int i = 0; i < 2; i++)
        #pragma unroll
        for (int j = 0; j < 8; j++)
            #pragma unroll
            for (int k = 0; k < 4; k++) acc[i][j][k] = 0.f;

    gemm_hi_core(smp, z_hi_g, bm, wupPT_hi_g, bn, 6400, acc, t);

    const float rsc = rsqrtf(1.f + BEPS);
    #pragma unroll
    for (int ms = 0; ms < 2; ms++)
        #pragma unroll
        for (int nt = 0; nt < 8; nt++) {
            size_t row0 = bm + wm * 32 + ms * 16 + (lane >> 2);
            int col0 = bn + wn * 64 + nt * 8 + 2 * (lane & 3);
            int c0 = col0 & 255, c1 = (col0 + 1) & 255;
            float s0 = gup[c0] * rsc, s1 = gup[c1] * rsc;
            float bi0 = bup[c0] * s0 + btup[c0];
            float bi1 = bup[c1] * s1 + btup[c1];
            *(float2*)&up2_g[row0 * 6400 + col0] =
                make_float2(fmaxf(acc[ms][nt][0] * s0 + bi0, 0.f),
                            fmaxf(acc[ms][nt][1] * s1 + bi1, 0.f));
            *(float2*)&up2_g[(row0 + 8) * 6400 + col0] =
                make_float2(fmaxf(acc[ms][nt][2] * s0 + bi0, 0.f),
                            fmaxf(acc[ms][nt][3] * s1 + bi1, 0.f));
        }
}

// ---------------------------------------------------------------------------
// g GEMM (1-pass, in-loop cvt): G[102400x144] = up2 * wd1
// ---------------------------------------------------------------------------
#define AS_STRIDE 36
#define GBS_STRIDE 152
__global__ __launch_bounds__(512, 1) void g_gemm_kernel(const float* __restrict__ wd1)
{
    __shared__ float As[128 * AS_STRIDE];
    __shared__ float Bs[32 * GBS_STRIDE];

    const int t = threadIdx.x;
    const int lane = t & 31, wid = t >> 5;
    const int wm = wid & 7, wn = wid >> 3;
    const int bm = blockIdx.x * 128;

    float acc[9][4];
    #pragma unroll
    for (int j = 0; j < 9; j++)
        #pragma unroll
        for (int k = 0; k < 4; k++) acc[j][k] = 0.f;

    const int ar = t >> 2, ak = (t & 3) * 8;

    for (int k0 = 0; k0 < 256; k0 += 32) {
        const float* asrc = &up2_g[(size_t)(bm + ar) * 256 + k0 + ak];
        float4 av0 = *(const float4*)asrc;
        float4 av1 = *(const float4*)(asrc + 4);
        float bvals[9];
        #pragma unroll
        for (int j = 0; j < 9; j++) {
            int i = t + j * 512;
            int row = i / 144, col = i - row * 144;
            bvals[j] = wd1[(size_t)(k0 + row) * 144 + col];
        }
        __syncthreads();
        *(float4*)&As[ar * AS_STRIDE + ak]     = av0;
        *(float4*)&As[ar * AS_STRIDE + ak + 4] = av1;
        #pragma unroll
        for (int j = 0; j < 9; j++) {
            int i = t + j * 512;
            int row = i / 144, col = i - row * 144;
            Bs[row * GBS_STRIDE + col] = bvals[j];
        }
        __syncthreads();

        #pragma unroll
        for (int ks = 0; ks < 4; ks++) {
            const int col = ks * 8 + (lane & 3);
            uint32_t ah[4];
            {
                int mb = wm * 16 + (lane >> 2);
                ah[0] = cvt_hi(As[mb * AS_STRIDE + col]);
                ah[1] = cvt_hi(As[(mb + 8) * AS_STRIDE + col]);
                ah[2] = cvt_hi(As[mb * AS_STRIDE + col + 4]);
                ah[3] = cvt_hi(As[(mb + 8) * AS_STRIDE + col + 4]);
            }
            const int row = ks * 8 + (lane & 3);
            #pragma unroll
            for (int nt = 0; nt < 9; nt++) {
                int nb = wn * 72 + nt * 8 + (lane >> 2);
                uint32_t bh[2];
                bh[0] = cvt_hi(Bs[row * GBS_STRIDE + nb]);
                bh[1] = cvt_hi(Bs[(row + 4) * GBS_STRIDE + nb]);
                mma_tf32(acc[nt], ah, bh);
            }
        }
    }

    #pragma unroll
    for (int nt = 0; nt < 9; nt++) {
        int row0 = bm + wm * 16 + (lane >> 2);
        int col0 = wn * 72 + nt * 8 + 2 * (lane & 3);
        *(float2*)&G_g[(size_t)row0 * 144 + col0] = make_float2(acc[nt][0], acc[nt][1]);
        *(float2*)&G_g[(size_t)(row0 + 8) * 144 + col0] = make_float2(acc[nt][2], acc[nt][3]);
    }
}

// ---------------------------------------------------------------------------
// softmax over minD -> w_g
// ---------------------------------------------------------------------------
__global__ __launch_bounds__(512) void softmax_kernel(const float* __restrict__ minD)
{
    __shared__ float red[32];
    const int b = blockIdx.x;
    const int t = threadIdx.x;
    const int lane = t & 31, wid = t >> 5;

    float m = minD[(size_t)b * 512 + t];
    float a = -m;
    float v = a;
    #pragma unroll
    for (int off = 16; off; off >>= 1) v = fmaxf(v, __shfl_xor_sync(0xffffffffu, v, off));
    if (!lane) red[wid] = v;
    __syncthreads();
    if (t == 0) {
        float r = red[0];
        for (int i = 1; i < 16; i++) r = fmaxf(r, red[i]);
        red[16] = r;
    }
    __syncthreads();
    float amax = red[16];
    float e = expf(a - amax);
    float sv = e;
    #pragma unroll
    for (int off = 16; off; off >>= 1) sv += __shfl_xor_sync(0xffffffffu, sv, off);
    __syncthreads();
    if (!lane) red[wid] = sv;
    __syncthreads();
    if (t == 0) {
        float r = 0.f;
        for (int i = 0; i < 16; i++) r += red[i];
        red[16] = r;
    }
    __syncthreads();
    w_g[(size_t)b * 512 + t] = e * (1.f / red[16]);
}

// ---------------------------------------------------------------------------
// z GEMM (FFMA f32x2): z = w * proto; epilogue emits z hi only
// ---------------------------------------------------------------------------
__global__ __launch_bounds__(256) void z_gemm_kernel(const float* __restrict__ proto)
{
    __shared__ __align__(16) float As2[16][128];
    __shared__ __align__(16) float Bs2[16][64];
    const int bn = blockIdx.x * 64;
    const int bm = blockIdx.y * 128;
    const int t = threadIdx.x;
    const int tx = t & 15, ty = t >> 4;

    unsigned long long acc[4][4];
    #pragma unroll
    for (int i = 0; i < 4; i++)
        #pragma unroll
        for (int j = 0; j < 4; j++) acc[i][j] = 0ull;

    for (int k0 = 0; k0 < 512; k0 += 16) {
        #pragma unroll
        for (int s = t; s < 512; s += 256) {
            int r = s >> 2, kq = (s & 3) << 2;
            float4 v = *(const float4*)&w_g[(size_t)(bm + r) * 512 + k0 + kq];
            As2[kq + 0][r] = v.x; As2[kq + 1][r] = v.y;
            As2[kq + 2][r] = v.z; As2[kq + 3][r] = v.w;
        }
        {
            int kk = t >> 4, n4 = (t & 15) << 2;
            *(float4*)&Bs2[kk][n4] = *(const float4*)&proto[(size_t)(k0 + kk) * 256 + bn + n4];
        }
        __syncthreads();
        #pragma unroll
        for (int kk = 0; kk < 16; kk++) {
            ulonglong2 a01 = *(const ulonglong2*)&As2[kk][ty * 8];
            ulonglong2 a23 = *(const ulonglong2*)&As2[kk][ty * 8 + 4];
            float4 bv = *(const float4*)&Bs2[kk][tx * 4];
            unsigned long long bd0 = pack2(bv.x, bv.x), bd1 = pack2(bv.y, bv.y);
            unsigned long long bd2 = pack2(bv.z, bv.z), bd3 = pack2(bv.w, bv.w);
            acc[0][0] = ffma2(a01.x, bd0, acc[0][0]); acc[0][1] = ffma2(a01.x, bd1, acc[0][1]);
            acc[0][2] = ffma2(a01.x, bd2, acc[0][2]); acc[0][3] = ffma2(a01.x, bd3, acc[0][3]);
            acc[1][0] = ffma2(a01.y, bd0, acc[1][0]); acc[1][1] = ffma2(a01.y, bd1, acc[1][1]);
            acc[1][2] = ffma2(a01.y, bd2, acc[1][2]); acc[1][3] = ffma2(a01.y, bd3, acc[1][3]);
            acc[2][0] = ffma2(a23.x, bd0, acc[2][0]); acc[2][1] = ffma2(a23.x, bd1, acc[2][1]);
            acc[2][2] = ffma2(a23.x, bd2, acc[2][2]); acc[2][3] = ffma2(a23.x, bd3, acc[2][3]);
            acc[3][0] = ffma2(a23.y, bd0, acc[3][0]); acc[3][1] = ffma2(a23.y, bd1, acc[3][1]);
            acc[3][2] = ffma2(a23.y, bd2, acc[3][2]); acc[3][3] = ffma2(a23.y, bd3, acc[3][3]);
        }
        __syncthreads();
    }

    #pragma unroll
    for (int mp = 0; mp < 4; mp++) {
        int m0 = bm + ty * 8 + mp * 2;
        float2 f0 = unpack2(acc[mp][0]), f1 = unpack2(acc[mp][1]);
        float2 f2 = unpack2(acc[mp][2]), f3 = unpack2(acc[mp][3]);
        float rows[2][4] = {{f0.x, f1.x, f2.x, f3.x}, {f0.y, f1.y, f2.y, f3.y}};
        #pragma unroll
        for (int rr = 0; rr < 2; rr++) {
            uint4 hi;
            hi.x = cvt_hi(rows[rr][0]);
            hi.y = cvt_hi(rows[rr][1]);
            hi.z = cvt_hi(rows[rr][2]);
            hi.w = cvt_hi(rows[rr][3]);
            size_t idx = (size_t)(m0 + rr) * 256 + bn + tx * 4;
            *(uint4*)&z_hi_g[idx] = hi;
        }
    }
}

// ---------------------------------------------------------------------------
// dec2: d1 = scatter(G)+BN+relu, then d2, d3. 2 images per block.
// ---------------------------------------------------------------------------
__global__ __launch_bounds__(256) void dec2_kernel(
    const float* __restrict__ bd1,
    const float* __restrict__ gd1, const float* __restrict__ btd1,
    const float* __restrict__ wd2, const float* __restrict__ bd2,
    const float* __restrict__ gd2, const float* __restrict__ btd2,
    const float* __restrict__ wd3, const float* __restrict__ bd3,
    float* __restrict__ out)
{
    extern __shared__ float sm[];
    float* Gs   = sm;                 // 2 * 3600
    float* d1s  = Gs + 7200;          // 2 * 784
    float* d2s  = d1s + 1568;         // 2 * 1568
    float* wd2s = d2s + 3136;         // 1152
    float* wd3s = wd2s + 1152;        // 72

    const int t = threadIdx.x;
    const int b0 = blockIdx.x * 2;
    const float rs = rsqrtf(1.f + BEPS);

    for (int i = t; i < 7200; i += 256) Gs[i] = G_g[(size_t)b0 * 3600 + i];
    for (int i = t; i < 1152; i += 256) wd2s[i] = wd2[i];
    if (t < 72) wd3s[t] = wd3[t];
    __syncthreads();

    for (int idx = t; idx < 1568; idx += 256) {
        int img = idx / 784, r = idx - img * 784;
        int o = r / 49, pos = r - o * 49;
        int oi = pos / 7, oj = pos % 7;
        int y0 = max(oi - 2, 0), y1 = min(oi, 4);
        int x0 = max(oj - 2, 0), x1 = min(oj, 4);
        float sum = 0.f;
        const float* Gb = &Gs[img * 3600];
        for (int y = y0; y <= y1; y++) {
            int ki = oi - y;
            for (int xx = x0; xx <= x1; xx++) {
                int kj = oj - xx;
                sum += Gb[(y * 5 + xx) * 144 + o * 9 + ki * 3 + kj];
            }
        }
        float s = gd1[o] * rs;
        d1s[img * 784 + o * 49 + pos] = fmaxf((sum + bd1[o]) * s + btd1[o], 0.f);
    }
    __syncthreads();

    if (t < 196) {
        float acc2[2][8];
        #pragma unroll
        for (int a = 0; a < 2; a++)
            #pragma unroll
            for (int o = 0; o < 8; o++) acc2[a][o] = 0.f;
        int i = t / 14, j = t % 14;
        int ylo = i / 2, yhi = min((i + 1) / 2, 6);
        int xlo = j / 2, xhi = min((j + 1) / 2, 6);
        for (int c = 0; c < 16; c++) {
            for (int y = ylo; y <= yhi; y++) {
                int ki = i - 2 * y + 1;
                for (int xx = xlo; xx <= xhi; xx++) {
                    int kj = j - 2 * xx + 1;
                    float u0 = d1s[0 * 784 + c * 49 + y * 7 + xx];
                    float u1 = d1s[1 * 784 + c * 49 + y * 7 + xx];
                    #pragma unroll
                    for (int o = 0; o < 8; o++) {
                        float wv = wd2s[((c * 8 + o) * 3 + ki) * 3 + kj];
                        acc2[0][o] += u0 * wv;
                        acc2[1][o] += u1 * wv;
                    }
                }
            }
        }
        #pragma unroll
        for (int o = 0; o < 8; o++) {
            float s = gd2[o] * rs;
            float bias = bd2[o] * s + btd2[o];
            #pragma unroll
            for (int a = 0; a < 2; a++)
                d2s[a * 1568 + o * 196 + t] = fmaxf(acc2[a][o] * s + bias, 0.f);
        }
    }
    __syncthreads();

    const float bb3 = bd3[0];
    for (int idx = t; idx < 1568; idx += 256) {
        int a = idx / 784, p = idx - a * 784, i = p / 28, j = p % 28;
        int ylo = i / 2, yhi = min((i + 1) / 2, 13);
        int xlo = j / 2, xhi = min((j + 1) / 2, 13);
        float acc3 = bb3;
        for (int c = 0; c < 8; c++) {
            for (int y = ylo; y <= yhi; y++) {
                int ki = i - 2 * y + 1;
                for (int xx = xlo; xx <= xhi; xx++) {
                    int kj = j - 2 * xx + 1;
                    acc3 += d2s[a * 1568 + c * 196 + y * 14 + xx] * wd3s[c * 9 + ki * 3 + kj];
                }
            }
        }
        out[(size_t)(b0 + a) * 784 + p] = 1.f / (1.f + expf(-acc3));
    }
}

// ---------------------------------------------------------------------------
extern "C" void kernel_launch(void* const* d_in, const int* in_sizes, int n_in,
                              void* d_out, int out_size)
{
    const float* x     = (const float*)d_in[0];
    const float* w1    = (const float*)d_in[1];
    const float* b1    = (const float*)d_in[2];
    const float* w2    = (const float*)d_in[3];
    const float* b2    = (const float*)d_in[4];
    const float* g2    = (const float*)d_in[5];
    const float* bt2   = (const float*)d_in[6];
    const float* w3    = (const float*)d_in[7];
    const float* b3    = (const float*)d_in[8];
    const float* proto = (const float*)d_in[9];
    const float* wup   = (const float*)d_in[10];
    const float* bup   = (const float*)d_in[11];
    const float* gup   = (const float*)d_in[12];
    const float* btup  = (const float*)d_in[13];
    const float* wd1   = (const float*)d_in[14];
    const float* bd1   = (const float*)d_in[15];
    const float* gd1   = (const float*)d_in[16];
    const float* btd1  = (const float*)d_in[17];
    const float* wd2   = (const float*)d_in[18];
    const float* bd2   = (const float*)d_in[19];
    const float* gd2   = (const float*)d_in[20];
    const float* btd2  = (const float*)d_in[21];
    const float* wd3   = (const float*)d_in[22];
    const float* bd3   = (const float*)d_in[23];

    float* out  = (float*)d_out;                 // (4096,1,28,28)
    float* minD = out + (size_t)NB * 784;        // (4096,512)

    prep_kernel<<<256, 256>>>(proto, w3, wup);
    enc12_kernel<<<NB, 128>>>(x, w1, b1, w2, b2, g2, bt2);
    conv3_kernel<<<NB, 256>>>(b3);
    x2_kernel<<<(NB * 25) / 8, 256>>>();
    init_mind_kernel<<<NB, 512>>>(minD);

    cudaFuncSetAttribute(xp_gemm_kernel, cudaFuncAttributeMaxDynamicSharedMemorySize, PIPE_SMEM);
    dim3 gx(512 / 128, (NB * 25) / 128);         // (4, 800)
    xp_gemm_kernel<<<gx, 256, PIPE_SMEM>>>(minD);

    softmax_kernel<<<NB, 512>>>(minD);

    dim3 gz(256 / 64, NB / 128);
    z_gemm_kernel<<<gz, 256>>>(proto);

    cudaFuncSetAttribute(up_gemm_kernel, cudaFuncAttributeMaxDynamicSharedMemorySize, PIPE_SMEM);
    dim3 gu(6400 / 128, NB / 128);               // (50, 32)
    up_gemm_kernel<<<gu, 256, PIPE_SMEM>>>(bup, gup, btup);

    g_gemm_kernel<<<(NB * 25) / 128, 512>>>(wd1);   // 800 blocks

    size_t smem2 = (size_t)(7200 + 1568 + 3136 + 1152 + 72) * sizeof(float); // 52,512 B
    cudaFuncSetAttribute(dec2_kernel, cudaFuncAttributeMaxDynamicSharedMemorySize, (int)smem2);
    dec2_kernel<<<NB / 2, 256, smem2>>>(bd1, gd1, btd1,
                                        wd2, bd2, gd2, btd2,
                                        wd3, bd3, out);
}